// round 11
// baseline (speedup 1.0000x reference)
#include <cuda_runtime.h>
#include <cstdint>

#define B_ 4
#define S_ 2048
#define D_ 1024
#define H_ 16
#define DK_ 64
#define DV_ 64
#define DOUT_ 1024

// Scratch: qh/kh/vh in (b,h,s,e) layout (tf32-rounded; qh pre-scaled by
// 0.125*log2e); concat in (b,s,h*DV) layout (tf32-rounded).
__device__ float g_qh[(size_t)B_*H_*S_*DK_];
__device__ float g_kh[(size_t)B_*H_*S_*DK_];
__device__ float g_vh[(size_t)B_*H_*S_*DV_];
__device__ float g_cat[(size_t)B_*S_*H_*DV_];

// ---------------------------------------------------------------------------
// PTX helpers
// ---------------------------------------------------------------------------
__device__ __forceinline__ uint32_t f2tf(float f) {
    uint32_t u;
    asm("cvt.rna.tf32.f32 %0, %1;" : "=r"(u) : "f"(f));
    return u;
}

__device__ __forceinline__ void mma_tf32(float* d, const uint32_t* a, const uint32_t* b) {
    asm volatile(
        "mma.sync.aligned.m16n8k8.row.col.f32.tf32.tf32.f32 "
        "{%0,%1,%2,%3}, {%4,%5,%6,%7}, {%8,%9}, {%0,%1,%2,%3};\n"
        : "+f"(d[0]), "+f"(d[1]), "+f"(d[2]), "+f"(d[3])
        : "r"(a[0]), "r"(a[1]), "r"(a[2]), "r"(a[3]), "r"(b[0]), "r"(b[1]));
}

__device__ __forceinline__ void cpa16(uint32_t dst, const void* src) {
    asm volatile("cp.async.cg.shared.global [%0], [%1], 16;\n" :: "r"(dst), "l"(src));
}
__device__ __forceinline__ void cpa_commit() {
    asm volatile("cp.async.commit_group;\n");
}
template <int N>
__device__ __forceinline__ void cpa_wait() {
    asm volatile("cp.async.wait_group %0;\n" :: "n"(N));
}

#define QSCALE (0.125f * 1.4426950408889634f)

// GEMM smem strides (floats): A rows of BK=32 + 4 pad; B rows of 128 + 8 pad.
// Bank audit: A frag addr (m+g)*36 + kr + tig -> 4g+tig' spans 32 banks;
// B frag addr (kr+tig)*136 + n : 8 consecutive n per g -> conflict-free.
#define AP2 36
#define BP 136
#define ABUF2 (128 * AP2)      // 4608 floats / buffer
#define BBUF2 (32 * BP)        // 4352 floats / buffer
#define SMEM_GEMM ((2 * ABUF2 + 2 * BBUF2) * 4)   // 71,680 B

// One BK=32 buffer: warp tile 64(m) x 32(n), 4x4 m16n8k8 frags, 4 k-steps.
__device__ __forceinline__ void mma_compute32(const float* As, const float* Bs,
                                              float acc[4][4][4],
                                              int wm, int wn, int g, int tig)
{
#pragma unroll
    for (int ks = 0; ks < 4; ++ks) {
        const int kr = ks * 8;
        uint32_t a[4][4];
#pragma unroll
        for (int mf = 0; mf < 4; ++mf) {
            const int m = wm * 64 + mf * 16;
            a[mf][0] = f2tf(As[(m + g)     * AP2 + kr + tig]);
            a[mf][1] = f2tf(As[(m + g + 8) * AP2 + kr + tig]);
            a[mf][2] = f2tf(As[(m + g)     * AP2 + kr + tig + 4]);
            a[mf][3] = f2tf(As[(m + g + 8) * AP2 + kr + tig + 4]);
        }
        uint32_t b[4][2];
#pragma unroll
        for (int nf = 0; nf < 4; ++nf) {
            const int n = wn * 32 + nf * 8 + g;
            b[nf][0] = f2tf(Bs[(kr + tig)     * BP + n]);
            b[nf][1] = f2tf(Bs[(kr + tig + 4) * BP + n]);
        }
#pragma unroll
        for (int mf = 0; mf < 4; ++mf)
#pragma unroll
            for (int nf = 0; nf < 4; ++nf)
                mma_tf32(acc[mf][nf], a[mf], b[nf]);
    }
}

// ---------------------------------------------------------------------------
// Kernel 1: per-head projections.  Block tile 128x128 (2 heads), BK=32,
// double-buffered dynamic smem, ONE __syncthreads per k-iteration.
// Epilogue writes tf32-rounded outputs; z==0 (Q) pre-scaled by QSCALE.
// ---------------------------------------------------------------------------
__global__ __launch_bounds__(256, 2) void proj_mma(
    const float* __restrict__ q, const float* __restrict__ k, const float* __restrict__ v,
    const float* __restrict__ Wq, const float* __restrict__ Wk, const float* __restrict__ Wv,
    const float* __restrict__ bq, const float* __restrict__ bk, const float* __restrict__ bv)
{
    extern __shared__ float smg[];
    float* Abuf[2] = { smg, smg + ABUF2 };
    float* Bbuf[2] = { smg + 2 * ABUF2, smg + 2 * ABUF2 + BBUF2 };

    const int z = blockIdx.z;
    const float* X    = (z == 0) ? q  : (z == 1) ? k  : v;
    const float* W    = (z == 0) ? Wq : (z == 1) ? Wk : Wv;
    const float* bias = (z == 0) ? bq : (z == 1) ? bk : bv;
    const float osc   = (z == 0) ? QSCALE : 1.0f;
    float* Out        = (z == 0) ? g_qh : (z == 1) ? g_kh : g_vh;

    const int h0 = blockIdx.y * 2;
    const int m0 = blockIdx.x * 128;
    const int b  = m0 >> 11;
    const int s0 = m0 & (S_ - 1);

    const float* Xb = X + (size_t)m0 * D_;

    const int tid = threadIdx.x;
    const int wid = tid >> 5, lane = tid & 31;
    const int wm = wid >> 2, wn = wid & 3;
    const int g = lane >> 2, tig = lane & 3;

    // loaders: A 128 rows x 32 k (2 threads/row, 16 floats each);
    //          B 32 rows x 128 n (8 threads/row, 16 floats each).
    const int am = tid >> 1, aj = (tid & 1) * 16;
    const int brow = tid >> 3, bcb = (tid & 7) * 16;
    const float* bsrc0 = W + (size_t)(h0 + (bcb >> 6)) * (D_ * DK_) + (bcb & 63);

    uint32_t aDst[2], bDst[2];
    aDst[0] = (uint32_t)__cvta_generic_to_shared(&Abuf[0][am * AP2 + aj]);
    aDst[1] = (uint32_t)__cvta_generic_to_shared(&Abuf[1][am * AP2 + aj]);
    bDst[0] = (uint32_t)__cvta_generic_to_shared(&Bbuf[0][brow * BP + bcb]);
    bDst[1] = (uint32_t)__cvta_generic_to_shared(&Bbuf[1][brow * BP + bcb]);

    float acc[4][4][4] = {};

    // prologue: tile 0 -> buffer 0
    {
        const float* as = Xb + (size_t)am * D_ + aj;
        cpa16(aDst[0], as);      cpa16(aDst[0] + 16, as + 4);
        cpa16(aDst[0] + 32, as + 8); cpa16(aDst[0] + 48, as + 12);
        const float* bs = bsrc0 + (size_t)brow * DK_;
        cpa16(bDst[0], bs);      cpa16(bDst[0] + 16, bs + 4);
        cpa16(bDst[0] + 32, bs + 8); cpa16(bDst[0] + 48, bs + 12);
        cpa_commit();
    }

    const int NT = D_ / 32;
#pragma unroll 1
    for (int t = 0; t < NT; ++t) {
        cpa_wait<0>();
        __syncthreads();   // publish buf t; prove buf t^1 drained
        if (t + 1 < NT) {
            const int kk = (t + 1) * 32;
            const int bi = (t + 1) & 1;
            const float* as = Xb + (size_t)am * D_ + kk + aj;
            cpa16(aDst[bi], as);      cpa16(aDst[bi] + 16, as + 4);
            cpa16(aDst[bi] + 32, as + 8); cpa16(aDst[bi] + 48, as + 12);
            const float* bs = bsrc0 + (size_t)(kk + brow) * DK_;
            cpa16(bDst[bi], bs);      cpa16(bDst[bi] + 16, bs + 4);
            cpa16(bDst[bi] + 32, bs + 8); cpa16(bDst[bi] + 48, bs + 12);
            cpa_commit();
        }
        mma_compute32(Abuf[t & 1], Bbuf[t & 1], acc, wm, wn, g, tig);
    }

#pragma unroll
    for (int nf = 0; nf < 4; ++nf) {
        const int c = wn * 32 + nf * 8 + tig * 2;
        const int h = h0 + (c >> 6);
        const int e = c & 63;
        const float b0v = bias[h * DK_ + e];
        const float b1v = bias[h * DK_ + e + 1];
        float* Ob = Out + ((size_t)(b * H_ + h) * S_ + s0) * DK_ + e;
#pragma unroll
        for (int mf = 0; mf < 4; ++mf) {
            const int r = wm * 64 + mf * 16 + g;
            uint2 u0, u1;
            u0.x = f2tf((acc[mf][nf][0] + b0v) * osc);
            u0.y = f2tf((acc[mf][nf][1] + b1v) * osc);
            u1.x = f2tf((acc[mf][nf][2] + b0v) * osc);
            u1.y = f2tf((acc[mf][nf][3] + b1v) * osc);
            *(uint2*)(Ob + (size_t)r * DK_) = u0;
            *(uint2*)(Ob + (size_t)(r + 8) * DK_) = u1;
        }
    }
}

// ---------------------------------------------------------------------------
// Kernel 2: tensor-core flash attention (Q/K/V pre-tf32, Q pre-scaled).
// Single __syncthreads per chunk: wait -> sync -> prefetch(next) -> compute.
// ---------------------------------------------------------------------------
#define QP 68
#define KP 68
#define VP 72
#define KBUF (64 * KP)
#define VBUF (64 * VP)
#define SM_K (128 * QP)
#define SM_V (SM_K + 2 * KBUF)
#define SM_M (SM_V + 2 * VBUF)
#define SMEM_ATTN ((SM_M + 128) * 4)

__global__ __launch_bounds__(256, 2) void attn_mma(const int* __restrict__ mask)
{
    extern __shared__ float sm[];
    uint32_t* Qs = (uint32_t*)sm;
    uint32_t* Ks = (uint32_t*)(sm + SM_K);
    uint32_t* Vs = (uint32_t*)(sm + SM_V);
    int*      Ms = (int*)(sm + SM_M);

    const int bh = blockIdx.y;
    const int b = bh >> 4, h = bh & 15;
    const int q0 = blockIdx.x * 128;

    const float* Qg = g_qh + ((size_t)bh * S_ + q0) * DK_;
    const float* Kg = g_kh + (size_t)bh * S_ * DK_;
    const float* Vg = g_vh + (size_t)bh * S_ * DK_;
    const int* mk = mask + (size_t)b * S_;

    const int tid = threadIdx.x;
    const int w = tid >> 5, lane = tid & 31;
    const int g = lane >> 2, t = lane & 3;
    const int lo = t & 1;
    const int sh = t >> 1, sh2 = sh + 2;

    // Q already scaled and tf32-rounded: plain vectorized copy.
    for (int i = tid; i < 512; i += 256) {
        const int row = i >> 2, c4 = (i & 3) * 16;
        *(uint4*)(&Qs[row * QP + c4])      = *(const uint4*)(Qg + (size_t)row * DK_ + c4);
        *(uint4*)(&Qs[row * QP + c4 + 4])  = *(const uint4*)(Qg + (size_t)row * DK_ + c4 + 4);
        *(uint4*)(&Qs[row * QP + c4 + 8])  = *(const uint4*)(Qg + (size_t)row * DK_ + c4 + 8);
        *(uint4*)(&Qs[row * QP + c4 + 12]) = *(const uint4*)(Qg + (size_t)row * DK_ + c4 + 12);
    }

    // prologue: chunk 0 into buffer 0
    {
#pragma unroll
        for (int j = 0; j < 4; ++j) {
            const int idx = tid + j * 256;
            const int row = idx >> 4, c = (idx & 15) * 4;
            cpa16((uint32_t)__cvta_generic_to_shared(&Ks[row * KP + c]),
                  Kg + (size_t)row * DK_ + c);
            cpa16((uint32_t)__cvta_generic_to_shared(&Vs[row * VP + c]),
                  Vg + (size_t)row * DK_ + c);
        }
        if (tid < 16)
            cpa16((uint32_t)__cvta_generic_to_shared(&Ms[tid * 4]), mk + tid * 4);
        cpa_commit();
    }

    float oacc[8][4] = {};
    float mold0 = -1e30f, mold1 = -1e30f;
    float lp0 = 0.0f, lp1 = 0.0f;

    const uint32_t* qbase = Qs + (w * 16 + g) * QP;

    const int NCH = S_ / 64;
#pragma unroll 1
    for (int chunk = 0; chunk < NCH; ++chunk) {
        const int bi = chunk & 1;

        cpa_wait<0>();
        __syncthreads();   // publish buf bi; prove buf bi^1 drained

        if (chunk + 1 < NCH) {
            const int kc = (chunk + 1) * 64;
            const int bo2 = bi ^ 1;
            uint32_t* kd = Ks + bo2 * KBUF;
            uint32_t* vd = Vs + bo2 * VBUF;
#pragma unroll
            for (int j = 0; j < 4; ++j) {
                const int idx = tid + j * 256;
                const int row = idx >> 4, c = (idx & 15) * 4;
                cpa16((uint32_t)__cvta_generic_to_shared(&kd[row * KP + c]),
                      Kg + (size_t)(kc + row) * DK_ + c);
                cpa16((uint32_t)__cvta_generic_to_shared(&vd[row * VP + c]),
                      Vg + (size_t)(kc + row) * DK_ + c);
            }
            if (tid < 16)
                cpa16((uint32_t)__cvta_generic_to_shared(&Ms[bo2 * 64 + tid * 4]),
                      mk + kc + tid * 4);
            cpa_commit();
        }

        const uint32_t* Kb = Ks + bi * KBUF;
        const uint32_t* Vb = Vs + bi * VBUF;
        const int*      Mb = Ms + bi * 64;

        // --- scores: S = Q @ K^T (no conversions) ---
        float sc[8][4] = {};
#pragma unroll
        for (int kb = 0; kb < 8; ++kb) {
            uint32_t a[4];
            const uint32_t* qr = qbase + kb * 8 + t;
            a[0] = qr[0];
            a[1] = qr[8 * QP];
            a[2] = qr[4];
            a[3] = qr[8 * QP + 4];
#pragma unroll
            for (int nf = 0; nf < 8; ++nf) {
                uint32_t bb[2];
                const uint32_t* kr = Kb + (nf * 8 + g) * KP + kb * 8 + t;
                bb[0] = kr[0];
                bb[1] = kr[4];
                mma_tf32(sc[nf], a, bb);
            }
        }

        // --- mask + row max ---
        float tm0 = -1e30f, tm1 = -1e30f;
#pragma unroll
        for (int nf = 0; nf < 8; ++nf) {
            const int ma = Mb[nf * 8 + 2 * t];
            const int mb = Mb[nf * 8 + 2 * t + 1];
            if (!ma) { sc[nf][0] = -1e30f; sc[nf][2] = -1e30f; }
            if (!mb) { sc[nf][1] = -1e30f; sc[nf][3] = -1e30f; }
            tm0 = fmaxf(tm0, fmaxf(sc[nf][0], sc[nf][1]));
            tm1 = fmaxf(tm1, fmaxf(sc[nf][2], sc[nf][3]));
        }
        tm0 = fmaxf(tm0, __shfl_xor_sync(0xffffffffu, tm0, 1));
        tm0 = fmaxf(tm0, __shfl_xor_sync(0xffffffffu, tm0, 2));
        tm1 = fmaxf(tm1, __shfl_xor_sync(0xffffffffu, tm1, 1));
        tm1 = fmaxf(tm1, __shfl_xor_sync(0xffffffffu, tm1, 2));

        const float mn0 = fmaxf(mold0, tm0);
        const float mn1 = fmaxf(mold1, tm1);
        const float f0 = exp2f(mold0 - mn0);
        const float f1 = exp2f(mold1 - mn1);
        mold0 = mn0; mold1 = mn1;

        // --- exp + partial sums; overwrite sc with tf32 bits of P ---
        float cs0 = 0.0f, cs1 = 0.0f;
#pragma unroll
        for (int nf = 0; nf < 8; ++nf) {
            const float p0 = exp2f(sc[nf][0] - mn0);
            const float p1 = exp2f(sc[nf][1] - mn0);
            const float p2 = exp2f(sc[nf][2] - mn1);
            const float p3 = exp2f(sc[nf][3] - mn1);
            cs0 += p0 + p1;
            cs1 += p2 + p3;
            sc[nf][0] = __uint_as_float(f2tf(p0));
            sc[nf][1] = __uint_as_float(f2tf(p1));
            sc[nf][2] = __uint_as_float(f2tf(p2));
            sc[nf][3] = __uint_as_float(f2tf(p3));
        }
        lp0 = lp0 * f0 + cs0;
        lp1 = lp1 * f1 + cs1;

#pragma unroll
        for (int nf = 0; nf < 8; ++nf) {
            oacc[nf][0] *= f0; oacc[nf][1] *= f0;
            oacc[nf][2] *= f1; oacc[nf][3] *= f1;
        }

        // --- O += P @ V ; C-frag -> A-frag via quad shuffles (bit-exact) ---
#pragma unroll
        for (int kb = 0; kb < 8; ++kb) {
            const uint32_t u0 = __float_as_uint(sc[kb][0]);
            const uint32_t u1 = __float_as_uint(sc[kb][1]);
            const uint32_t u2 = __float_as_uint(sc[kb][2]);
            const uint32_t u3 = __float_as_uint(sc[kb][3]);
            uint32_t a[4];
            {
                const uint32_t x0 = __shfl_sync(0xffffffffu, u0, sh, 4);
                const uint32_t x1 = __shfl_sync(0xffffffffu, u1, sh, 4);
                a[0] = lo ? x1 : x0;
                const uint32_t x2 = __shfl_sync(0xffffffffu, u2, sh, 4);
                const uint32_t x3 = __shfl_sync(0xffffffffu, u3, sh, 4);
                a[1] = lo ? x3 : x2;
                const uint32_t y0 = __shfl_sync(0xffffffffu, u0, sh2, 4);
                const uint32_t y1 = __shfl_sync(0xffffffffu, u1, sh2, 4);
                a[2] = lo ? y1 : y0;
                const uint32_t y2 = __shfl_sync(0xffffffffu, u2, sh2, 4);
                const uint32_t y3 = __shfl_sync(0xffffffffu, u3, sh2, 4);
                a[3] = lo ? y3 : y2;
            }
#pragma unroll
            for (int nf = 0; nf < 8; ++nf) {
                uint32_t bb[2];
                const uint32_t* vr = Vb + (kb * 8 + t) * VP + nf * 8 + g;
                bb[0] = vr[0];
                bb[1] = vr[4 * VP];
                mma_tf32(oacc[nf], a, bb);
            }
        }
    }

    // --- epilogue: quad-reduce l, normalize, write concat as tf32 bits ---
    lp0 += __shfl_xor_sync(0xffffffffu, lp0, 1);
    lp0 += __shfl_xor_sync(0xffffffffu, lp0, 2);
    lp1 += __shfl_xor_sync(0xffffffffu, lp1, 1);
    lp1 += __shfl_xor_sync(0xffffffffu, lp1, 2);
    const float inv0 = 1.0f / lp0;
    const float inv1 = 1.0f / lp1;

    const int r0 = q0 + w * 16 + g;
    float* cat0 = g_cat + ((size_t)b * S_ + r0) * (H_ * DV_) + (size_t)h * DV_;
    float* cat1 = cat0 + (size_t)8 * (H_ * DV_);
#pragma unroll
    for (int nf = 0; nf < 8; ++nf) {
        const int c = nf * 8 + 2 * t;
        uint2 u0, u1;
        u0.x = f2tf(oacc[nf][0] * inv0);
        u0.y = f2tf(oacc[nf][1] * inv0);
        u1.x = f2tf(oacc[nf][2] * inv1);
        u1.y = f2tf(oacc[nf][3] * inv1);
        *(uint2*)(cat0 + c) = u0;
        *(uint2*)(cat1 + c) = u1;
    }
}

// ---------------------------------------------------------------------------
// Kernel 3: output projection, BK=32 single-sync (same structure as proj).
// ---------------------------------------------------------------------------
__global__ __launch_bounds__(256, 2) void out_mma(
    const float* __restrict__ Wo, const float* __restrict__ bo, float* __restrict__ out)
{
    extern __shared__ float smg[];
    float* Abuf[2] = { smg, smg + ABUF2 };
    float* Bbuf[2] = { smg + 2 * ABUF2, smg + 2 * ABUF2 + BBUF2 };

    const int m0 = blockIdx.x * 128;
    const int n0 = blockIdx.y * 128;

    const float* Ab = g_cat + (size_t)m0 * DOUT_;

    const int tid = threadIdx.x;
    const int wid = tid >> 5, lane = tid & 31;
    const int wm = wid >> 2, wn = wid & 3;
    const int g = lane >> 2, tig = lane & 3;

    const int am = tid >> 1, aj = (tid & 1) * 16;
    const int brow = tid >> 3, bcb = (tid & 7) * 16;
    const float* bsrc0 = Wo + n0 + bcb;

    uint32_t aDst[2], bDst[2];
    aDst[0] = (uint32_t)__cvta_generic_to_shared(&Abuf[0][am * AP2 + aj]);
    aDst[1] = (uint32_t)__cvta_generic_to_shared(&Abuf[1][am * AP2 + aj]);
    bDst[0] = (uint32_t)__cvta_generic_to_shared(&Bbuf[0][brow * BP + bcb]);
    bDst[1] = (uint32_t)__cvta_generic_to_shared(&Bbuf[1][brow * BP + bcb]);

    float acc[4][4][4] = {};

    {
        const float* as = Ab + (size_t)am * DOUT_ + aj;
        cpa16(aDst[0], as);      cpa16(aDst[0] + 16, as + 4);
        cpa16(aDst[0] + 32, as + 8); cpa16(aDst[0] + 48, as + 12);
        const float* bs = bsrc0 + (size_t)brow * DOUT_;
        cpa16(bDst[0], bs);      cpa16(bDst[0] + 16, bs + 4);
        cpa16(bDst[0] + 32, bs + 8); cpa16(bDst[0] + 48, bs + 12);
        cpa_commit();
    }

    const int NT = DOUT_ / 32;
#pragma unroll 1
    for (int t = 0; t < NT; ++t) {
        cpa_wait<0>();
        __syncthreads();
        if (t + 1 < NT) {
            const int kk = (t + 1) * 32;
            const int bi = (t + 1) & 1;
            const float* as = Ab + (size_t)am * DOUT_ + kk + aj;
            cpa16(aDst[bi], as);      cpa16(aDst[bi] + 16, as + 4);
            cpa16(aDst[bi] + 32, as + 8); cpa16(aDst[bi] + 48, as + 12);
            const float* bs = bsrc0 + (size_t)(kk + brow) * DOUT_;
            cpa16(bDst[bi], bs);      cpa16(bDst[bi] + 16, bs + 4);
            cpa16(bDst[bi] + 32, bs + 8); cpa16(bDst[bi] + 48, bs + 12);
            cpa_commit();
        }
        mma_compute32(Abuf[t & 1], Bbuf[t & 1], acc, wm, wn, g, tig);
    }

#pragma unroll
    for (int nf = 0; nf < 4; ++nf) {
        const int c = n0 + wn * 32 + nf * 8 + tig * 2;
        const float b0v = bo[c], b1v = bo[c + 1];
#pragma unroll
        for (int mf = 0; mf < 4; ++mf) {
            const int r = m0 + wm * 64 + mf * 16 + g;
            *(float2*)(out + (size_t)r * DOUT_ + c) =
                make_float2(acc[mf][nf][0] + b0v, acc[mf][nf][1] + b1v);
            *(float2*)(out + (size_t)(r + 8) * DOUT_ + c) =
                make_float2(acc[mf][nf][2] + b0v, acc[mf][nf][3] + b1v);
        }
    }
}

// ---------------------------------------------------------------------------
extern "C" void kernel_launch(void* const* d_in, const int* in_sizes, int n_in,
                              void* d_out, int out_size)
{
    const float* q  = (const float*)d_in[0];
    const float* k  = (const float*)d_in[1];
    const float* v  = (const float*)d_in[2];
    const int* mask = (const int*)d_in[3];
    const float* Wq = (const float*)d_in[4];
    const float* bq = (const float*)d_in[5];
    const float* Wk = (const float*)d_in[6];
    const float* bk = (const float*)d_in[7];
    const float* Wv = (const float*)d_in[8];
    const float* bv = (const float*)d_in[9];
    const float* Wo = (const float*)d_in[10];
    const float* bo = (const float*)d_in[11];
    float* out = (float*)d_out;

    cudaFuncSetAttribute(proj_mma, cudaFuncAttributeMaxDynamicSharedMemorySize, SMEM_GEMM);
    cudaFuncSetAttribute(attn_mma, cudaFuncAttributeMaxDynamicSharedMemorySize, SMEM_ATTN);
    cudaFuncSetAttribute(out_mma,  cudaFuncAttributeMaxDynamicSharedMemorySize, SMEM_GEMM);

    dim3 g1((B_ * S_) / 128, H_ / 2, 3);
    proj_mma<<<g1, 256, SMEM_GEMM>>>(q, k, v, Wq, Wk, Wv, bq, bk, bv);

    dim3 g2(S_ / 128, B_ * H_);
    attn_mma<<<g2, 256, SMEM_ATTN>>>(mask);

    dim3 g3((B_ * S_) / 128, DOUT_ / 128);
    out_mma<<<g3, 256, SMEM_GEMM>>>(Wo, bo, out);
}

// round 12
// speedup vs baseline: 1.3827x; 1.3827x over previous
#include <cuda_runtime.h>
#include <cuda_fp16.h>
#include <cstdint>

#define B_ 4
#define S_ 2048
#define D_ 1024
#define H_ 16
#define DK_ 64
#define DV_ 64
#define DOUT_ 1024

// Scratch, fp16: qh/kh/vh (b,h,s,e); qh pre-scaled by 0.125*log2e.
// cat stored as packed half2 words: [b*S+s][H*DV/2].
__device__ __half  g_qh[(size_t)B_*H_*S_*DK_];
__device__ __half  g_kh[(size_t)B_*H_*S_*DK_];
__device__ __half  g_vh[(size_t)B_*H_*S_*DV_];
__device__ uint32_t g_cat32[(size_t)B_*S_*(H_*DV_/2)];

// ---------------------------------------------------------------------------
// PTX helpers
// ---------------------------------------------------------------------------
__device__ __forceinline__ uint32_t packh2(float lo, float hi) {
    uint32_t u;
    asm("cvt.rn.f16x2.f32 %0, %1, %2;" : "=r"(u) : "f"(hi), "f"(lo));
    return u;
}

__device__ __forceinline__ void mma_f16(float* d, const uint32_t* a,
                                        uint32_t b0, uint32_t b1) {
    asm volatile(
        "mma.sync.aligned.m16n8k16.row.col.f32.f16.f16.f32 "
        "{%0,%1,%2,%3}, {%4,%5,%6,%7}, {%8,%9}, {%0,%1,%2,%3};\n"
        : "+f"(d[0]), "+f"(d[1]), "+f"(d[2]), "+f"(d[3])
        : "r"(a[0]), "r"(a[1]), "r"(a[2]), "r"(a[3]), "r"(b0), "r"(b1));
}

__device__ __forceinline__ void cpa16(uint32_t dst, const void* src) {
    asm volatile("cp.async.cg.shared.global [%0], [%1], 16;\n" :: "r"(dst), "l"(src));
}
__device__ __forceinline__ void cpa_commit() {
    asm volatile("cp.async.commit_group;\n");
}
template <int N>
__device__ __forceinline__ void cpa_wait() {
    asm volatile("cp.async.wait_group %0;\n" :: "n"(N));
}

#define QSCALE (0.125f * 1.4426950408889634f)

// fp32 GEMM smem strides (floats): A 16+4, B 128+8 (R10-proven).
#define AP 20
#define BP 136

// One BK=16 buffer = one m16n8k16 step per (mf,nf).  Warp tile 64x32.
// A packed from contiguous fp32 pairs; B packed from row pairs 2t/2t+1.
__device__ __forceinline__ void mma_f16_step(const float* As, const float* Bs,
                                             float acc[4][4][4],
                                             int wm, int wn, int g, int t)
{
    uint32_t a[4][4];
#pragma unroll
    for (int mf = 0; mf < 4; ++mf) {
        const int m = wm * 64 + mf * 16;
        float2 f0 = *(const float2*)&As[(m + g)     * AP + 2 * t];
        float2 f1 = *(const float2*)&As[(m + g + 8) * AP + 2 * t];
        float2 f2 = *(const float2*)&As[(m + g)     * AP + 2 * t + 8];
        float2 f3 = *(const float2*)&As[(m + g + 8) * AP + 2 * t + 8];
        a[mf][0] = packh2(f0.x, f0.y);
        a[mf][1] = packh2(f1.x, f1.y);
        a[mf][2] = packh2(f2.x, f2.y);
        a[mf][3] = packh2(f3.x, f3.y);
    }
#pragma unroll
    for (int nf = 0; nf < 4; ++nf) {
        const int n = wn * 32 + nf * 8 + g;
        uint32_t b0 = packh2(Bs[(2 * t)     * BP + n], Bs[(2 * t + 1) * BP + n]);
        uint32_t b1 = packh2(Bs[(2 * t + 8) * BP + n], Bs[(2 * t + 9) * BP + n]);
#pragma unroll
        for (int mf = 0; mf < 4; ++mf)
            mma_f16(acc[mf][nf], a[mf], b0, b1);
    }
}

// ---------------------------------------------------------------------------
// Kernel 1: per-head projections (fp16 mma, fp32 cp.async smem, R10 pipeline).
// Block tile 128x128 (2 heads), BK=16, NT=64.  Epilogue -> fp16 scratch,
// Q additionally scaled by QSCALE.
// ---------------------------------------------------------------------------
__global__ __launch_bounds__(256, 2) void proj_mma(
    const float* __restrict__ q, const float* __restrict__ k, const float* __restrict__ v,
    const float* __restrict__ Wq, const float* __restrict__ Wk, const float* __restrict__ Wv,
    const float* __restrict__ bq, const float* __restrict__ bk, const float* __restrict__ bv)
{
    const int z = blockIdx.z;
    const float* X    = (z == 0) ? q  : (z == 1) ? k  : v;
    const float* W    = (z == 0) ? Wq : (z == 1) ? Wk : Wv;
    const float* bias = (z == 0) ? bq : (z == 1) ? bk : bv;
    const float osc   = (z == 0) ? QSCALE : 1.0f;
    __half* Out       = (z == 0) ? g_qh : (z == 1) ? g_kh : g_vh;

    const int h0 = blockIdx.y * 2;
    const int m0 = blockIdx.x * 128;
    const int b  = m0 >> 11;
    const int s0 = m0 & (S_ - 1);

    const float* Xb = X + (size_t)m0 * D_;

    __shared__ float As[2][128 * AP];
    __shared__ float Bs[2][16 * BP];

    const int tid = threadIdx.x;
    const int wid = tid >> 5, lane = tid & 31;
    const int wm = wid >> 2, wn = wid & 3;
    const int g = lane >> 2, t = lane & 3;

    const int am = tid >> 1, aj = (tid & 1) * 8;
    const int brow = tid >> 4, bcb = (tid & 15) * 8;
    const float* bsrc0 = W + (size_t)(h0 + (bcb >> 6)) * (D_ * DK_) + (bcb & 63);

    uint32_t aDst[2], bDst[2];
    aDst[0] = (uint32_t)__cvta_generic_to_shared(&As[0][am * AP + aj]);
    aDst[1] = (uint32_t)__cvta_generic_to_shared(&As[1][am * AP + aj]);
    bDst[0] = (uint32_t)__cvta_generic_to_shared(&Bs[0][brow * BP + bcb]);
    bDst[1] = (uint32_t)__cvta_generic_to_shared(&Bs[1][brow * BP + bcb]);

    float acc[4][4][4] = {};

    {
        const float* as = Xb + (size_t)am * D_ + aj;
        cpa16(aDst[0], as);
        cpa16(aDst[0] + 16, as + 4);
        const float* bs = bsrc0 + (size_t)brow * DK_;
        cpa16(bDst[0], bs);
        cpa16(bDst[0] + 16, bs + 4);
        cpa_commit();
    }

    const int NT = D_ / 16;
#pragma unroll 1
    for (int it = 0; it < NT; ++it) {
        if (it + 1 < NT) {
            const int kk = (it + 1) * 16;
            const int bi = (it + 1) & 1;
            const float* as = Xb + (size_t)am * D_ + kk + aj;
            cpa16(aDst[bi], as);
            cpa16(aDst[bi] + 16, as + 4);
            const float* bs = bsrc0 + (size_t)(kk + brow) * DK_;
            cpa16(bDst[bi], bs);
            cpa16(bDst[bi] + 16, bs + 4);
            cpa_commit();
            cpa_wait<1>();
        } else {
            cpa_wait<0>();
        }
        __syncthreads();
        mma_f16_step(As[it & 1], Bs[it & 1], acc, wm, wn, g, t);
        __syncthreads();
    }

#pragma unroll
    for (int nf = 0; nf < 4; ++nf) {
        const int c = wn * 32 + nf * 8 + t * 2;
        const int h = h0 + (c >> 6);
        const int e = c & 63;
        const float b0v = bias[h * DK_ + e];
        const float b1v = bias[h * DK_ + e + 1];
        __half* Ob = Out + ((size_t)(b * H_ + h) * S_ + s0) * DK_ + e;
#pragma unroll
        for (int mf = 0; mf < 4; ++mf) {
            const int r = wm * 64 + mf * 16 + g;
            *(uint32_t*)(Ob + (size_t)r * DK_) =
                packh2((acc[mf][nf][0] + b0v) * osc, (acc[mf][nf][1] + b1v) * osc);
            *(uint32_t*)(Ob + (size_t)(r + 8) * DK_) =
                packh2((acc[mf][nf][2] + b0v) * osc, (acc[mf][nf][3] + b1v) * osc);
        }
    }
}

// ---------------------------------------------------------------------------
// Kernel 2: fp16 tensor-core flash attention.  Scratch is fp16 (Q pre-scaled).
// R10 pipeline (prefetch-early, wait<1>, 2 syncs).  Br=128, Bc=64.
// No shuffles: C-frag cols (2t,2t+1) == A-frag k-pair; P packs with one cvt.
// ---------------------------------------------------------------------------
#define QPW 36                       // words per 64-half row (32 data + 4 pad)
#define KBUFW (64 * QPW)             // 2304 words per K/V buffer
#define SM_K 4608                    // after Q (128*36)
#define SM_V (SM_K + 2 * KBUFW)      // 9216
#define SM_M (SM_V + 2 * KBUFW)      // 13824 (int words)
#define SMEM_ATTN ((SM_M + 128) * 4) // 55,808 B

__global__ __launch_bounds__(256, 2) void attn_mma(const int* __restrict__ mask)
{
    extern __shared__ uint32_t smw[];
    uint32_t* Qs = smw;
    int*      Msall = (int*)(smw + SM_M);

    const int bh = blockIdx.y;
    const int b = bh >> 4, h = bh & 15;
    const int q0 = blockIdx.x * 128;

    const __half* Qg = g_qh + ((size_t)bh * S_ + q0) * DK_;
    const __half* Kg = g_kh + (size_t)bh * S_ * DK_;
    const __half* Vg = g_vh + (size_t)bh * S_ * DK_;
    const int* mk = mask + (size_t)b * S_;

    const int tid = threadIdx.x;
    const int w = tid >> 5, lane = tid & 31;
    const int g = lane >> 2, t = lane & 3;

    // Q copy (fp16, pre-scaled): 128 rows x 32 words.
    const uint32_t* Qg32 = (const uint32_t*)Qg;
    for (int i = tid; i < 1024; i += 256) {
        const int row = i >> 3, ws = (i & 7) * 4;
        *(uint4*)(&Qs[row * QPW + ws]) = *(const uint4*)(Qg32 + row * 32 + ws);
    }

    // prologue: chunk 0 -> buffer 0 (K,V fp16: 64 rows x 32 words each)
    {
#pragma unroll
        for (int j = 0; j < 2; ++j) {
            const int idx = tid + j * 256;
            const int row = idx >> 3, hc = (idx & 7) * 8;   // half offset in row
            cpa16((uint32_t)__cvta_generic_to_shared(smw + SM_K + row * QPW + hc / 2),
                  Kg + (size_t)row * DK_ + hc);
            cpa16((uint32_t)__cvta_generic_to_shared(smw + SM_V + row * QPW + hc / 2),
                  Vg + (size_t)row * DK_ + hc);
        }
        if (tid < 16)
            cpa16((uint32_t)__cvta_generic_to_shared((uint32_t*)(Msall) + tid * 4),
                  mk + tid * 4);
        cpa_commit();
    }

    float oacc[8][4] = {};
    float mold0 = -1e30f, mold1 = -1e30f;
    float lp0 = 0.0f, lp1 = 0.0f;

    const uint32_t* qbase = Qs + (w * 16 + g) * QPW;

    const int NCH = S_ / 64;
#pragma unroll 1
    for (int chunk = 0; chunk < NCH; ++chunk) {
        const int bi = chunk & 1;

        if (chunk + 1 < NCH) {
            const int kc = (chunk + 1) * 64;
            const int bo2 = bi ^ 1;
#pragma unroll
            for (int j = 0; j < 2; ++j) {
                const int idx = tid + j * 256;
                const int row = idx >> 3, hc = (idx & 7) * 8;
                cpa16((uint32_t)__cvta_generic_to_shared(
                          smw + SM_K + bo2 * KBUFW + row * QPW + hc / 2),
                      Kg + (size_t)(kc + row) * DK_ + hc);
                cpa16((uint32_t)__cvta_generic_to_shared(
                          smw + SM_V + bo2 * KBUFW + row * QPW + hc / 2),
                      Vg + (size_t)(kc + row) * DK_ + hc);
            }
            if (tid < 16)
                cpa16((uint32_t)__cvta_generic_to_shared(
                          (uint32_t*)(Msall) + bo2 * 64 + tid * 4),
                      mk + kc + tid * 4);
            cpa_commit();
            cpa_wait<1>();
        } else {
            cpa_wait<0>();
        }
        __syncthreads();

        const uint32_t* Kw = smw + SM_K + bi * KBUFW;
        const unsigned short* Vh = (const unsigned short*)(smw + SM_V + bi * KBUFW);
        const int* Mb = Msall + bi * 64;

        // --- scores: S = Q @ K^T  (kb: 4 k16-steps over DK=64) ---
        float sc[8][4] = {};
#pragma unroll
        for (int kb = 0; kb < 4; ++kb) {
            uint32_t a[4];
            const uint32_t* qr = qbase + kb * 8 + t;
            a[0] = qr[0];
            a[1] = qr[8 * QPW];
            a[2] = qr[4];
            a[3] = qr[8 * QPW + 4];
#pragma unroll
            for (int nf = 0; nf < 8; ++nf) {
                const uint32_t* kr = Kw + (nf * 8 + g) * QPW + kb * 8 + t;
                mma_f16(sc[nf], a, kr[0], kr[4]);
            }
        }

        // --- mask + row max ---
        float tm0 = -1e30f, tm1 = -1e30f;
#pragma unroll
        for (int nf = 0; nf < 8; ++nf) {
            const int ma = Mb[nf * 8 + 2 * t];
            const int mb = Mb[nf * 8 + 2 * t + 1];
            if (!ma) { sc[nf][0] = -1e30f; sc[nf][2] = -1e30f; }
            if (!mb) { sc[nf][1] = -1e30f; sc[nf][3] = -1e30f; }
            tm0 = fmaxf(tm0, fmaxf(sc[nf][0], sc[nf][1]));
            tm1 = fmaxf(tm1, fmaxf(sc[nf][2], sc[nf][3]));
        }
        tm0 = fmaxf(tm0, __shfl_xor_sync(0xffffffffu, tm0, 1));
        tm0 = fmaxf(tm0, __shfl_xor_sync(0xffffffffu, tm0, 2));
        tm1 = fmaxf(tm1, __shfl_xor_sync(0xffffffffu, tm1, 1));
        tm1 = fmaxf(tm1, __shfl_xor_sync(0xffffffffu, tm1, 2));

        const float mn0 = fmaxf(mold0, tm0);
        const float mn1 = fmaxf(mold1, tm1);
        const float f0 = exp2f(mold0 - mn0);
        const float f1 = exp2f(mold1 - mn1);
        mold0 = mn0; mold1 = mn1;

        // --- exp + partial sums (P stays in sc as fp32) ---
        float cs0 = 0.0f, cs1 = 0.0f;
#pragma unroll
        for (int nf = 0; nf < 8; ++nf) {
            sc[nf][0] = exp2f(sc[nf][0] - mn0);
            sc[nf][1] = exp2f(sc[nf][1] - mn0);
            sc[nf][2] = exp2f(sc[nf][2] - mn1);
            sc[nf][3] = exp2f(sc[nf][3] - mn1);
            cs0 += sc[nf][0] + sc[nf][1];
            cs1 += sc[nf][2] + sc[nf][3];
        }
        lp0 = lp0 * f0 + cs0;
        lp1 = lp1 * f1 + cs1;

#pragma unroll
        for (int nf = 0; nf < 8; ++nf) {
            oacc[nf][0] *= f0; oacc[nf][1] *= f0;
            oacc[nf][2] *= f1; oacc[nf][3] *= f1;
        }

        // --- O += P @ V ;  P packs directly into A-frags (no shuffles) ---
#pragma unroll
        for (int kb = 0; kb < 4; ++kb) {
            uint32_t a[4];
            a[0] = packh2(sc[2 * kb][0],     sc[2 * kb][1]);
            a[1] = packh2(sc[2 * kb][2],     sc[2 * kb][3]);
            a[2] = packh2(sc[2 * kb + 1][0], sc[2 * kb + 1][1]);
            a[3] = packh2(sc[2 * kb + 1][2], sc[2 * kb + 1][3]);
            const int r0 = kb * 16 + 2 * t;
#pragma unroll
            for (int nf = 0; nf < 8; ++nf) {
                const int n = nf * 8 + g;
                uint32_t b0 = (uint32_t)Vh[r0 * 72 + n] |
                              ((uint32_t)Vh[(r0 + 1) * 72 + n] << 16);
                uint32_t b1 = (uint32_t)Vh[(r0 + 8) * 72 + n] |
                              ((uint32_t)Vh[(r0 + 9) * 72 + n] << 16);
                mma_f16(oacc[nf], a, b0, b1);
            }
        }
        __syncthreads();
    }

    // --- epilogue: quad-reduce l, normalize, write cat (half2 words) ---
    lp0 += __shfl_xor_sync(0xffffffffu, lp0, 1);
    lp0 += __shfl_xor_sync(0xffffffffu, lp0, 2);
    lp1 += __shfl_xor_sync(0xffffffffu, lp1, 1);
    lp1 += __shfl_xor_sync(0xffffffffu, lp1, 2);
    const float inv0 = 1.0f / lp0;
    const float inv1 = 1.0f / lp1;

    const int r0 = q0 + w * 16 + g;
    uint32_t* cat0 = g_cat32 + ((size_t)b * S_ + r0) * 512 + h * 32;
    uint32_t* cat1 = cat0 + (size_t)8 * 512;
#pragma unroll
    for (int nf = 0; nf < 8; ++nf) {
        const int cw = nf * 4 + t;
        cat0[cw] = packh2(oacc[nf][0] * inv0, oacc[nf][1] * inv0);
        cat1[cw] = packh2(oacc[nf][2] * inv1, oacc[nf][3] * inv1);
    }
}

// ---------------------------------------------------------------------------
// Kernel 3: output projection.  A = cat (fp16 words), B = Wo (fp32, packed
// in-register).  BK=16, R10 pipeline.
// ---------------------------------------------------------------------------
#define APW 12   // words per A row (8 data + 4 pad)

__global__ __launch_bounds__(256, 2) void out_mma(
    const float* __restrict__ Wo, const float* __restrict__ bo, float* __restrict__ out)
{
    const int m0 = blockIdx.x * 128;
    const int n0 = blockIdx.y * 128;

    const uint32_t* Ab = g_cat32 + (size_t)m0 * 512;

    __shared__ uint32_t As16[2][128 * APW];
    __shared__ float Bs[2][16 * BP];

    const int tid = threadIdx.x;
    const int wid = tid >> 5, lane = tid & 31;
    const int wm = wid >> 2, wn = wid & 3;
    const int g = lane >> 2, t = lane & 3;

    const int am = tid >> 1, aw = (tid & 1) * 4;    // A: 128 rows x 8 words
    const int brow = tid >> 4, bcb = (tid & 15) * 8;
    const float* bsrc0 = Wo + n0 + bcb;

    uint32_t aDst[2], bDst[2];
    aDst[0] = (uint32_t)__cvta_generic_to_shared(&As16[0][am * APW + aw]);
    aDst[1] = (uint32_t)__cvta_generic_to_shared(&As16[1][am * APW + aw]);
    bDst[0] = (uint32_t)__cvta_generic_to_shared(&Bs[0][brow * BP + bcb]);
    bDst[1] = (uint32_t)__cvta_generic_to_shared(&Bs[1][brow * BP + bcb]);

    float acc[4][4][4] = {};

    {
        cpa16(aDst[0], Ab + (size_t)am * 512 + aw);
        const float* bs = bsrc0 + (size_t)brow * DOUT_;
        cpa16(bDst[0], bs);
        cpa16(bDst[0] + 16, bs + 4);
        cpa_commit();
    }

    const int NT = DOUT_ / 16;
#pragma unroll 1
    for (int it = 0; it < NT; ++it) {
        if (it + 1 < NT) {
            const int bi = (it + 1) & 1;
            cpa16(aDst[bi], Ab + (size_t)am * 512 + (it + 1) * 8 + aw);
            const float* bs = bsrc0 + (size_t)((it + 1) * 16 + brow) * DOUT_;
            cpa16(bDst[bi], bs);
            cpa16(bDst[bi] + 16, bs + 4);
            cpa_commit();
            cpa_wait<1>();
        } else {
            cpa_wait<0>();
        }
        __syncthreads();

        const uint32_t* As = As16[it & 1];
        const float* Bsf = Bs[it & 1];
        uint32_t a[4][4];
#pragma unroll
        for (int mf = 0; mf < 4; ++mf) {
            const int m = wm * 64 + mf * 16;
            a[mf][0] = As[(m + g)     * APW + t];
            a[mf][1] = As[(m + g + 8) * APW + t];
            a[mf][2] = As[(m + g)     * APW + t + 4];
            a[mf][3] = As[(m + g + 8) * APW + t + 4];
        }
#pragma unroll
        for (int nf = 0; nf < 4; ++nf) {
            const int n = wn * 32 + nf * 8 + g;
            uint32_t b0 = packh2(Bsf[(2 * t)     * BP + n], Bsf[(2 * t + 1) * BP + n]);
            uint32_t b1 = packh2(Bsf[(2 * t + 8) * BP + n], Bsf[(2 * t + 9) * BP + n]);
#pragma unroll
            for (int mf = 0; mf < 4; ++mf)
                mma_f16(acc[mf][nf], a[mf], b0, b1);
        }
        __syncthreads();
    }

#pragma unroll
    for (int nf = 0; nf < 4; ++nf) {
        const int c = n0 + wn * 32 + nf * 8 + t * 2;
        const float b0v = bo[c], b1v = bo[c + 1];
#pragma unroll
        for (int mf = 0; mf < 4; ++mf) {
            const int r = m0 + wm * 64 + mf * 16 + g;
            *(float2*)(out + (size_t)r * DOUT_ + c) =
                make_float2(acc[mf][nf][0] + b0v, acc[mf][nf][1] + b1v);
            *(float2*)(out + (size_t)(r + 8) * DOUT_ + c) =
                make_float2(acc[mf][nf][2] + b0v, acc[mf][nf][3] + b1v);
        }
    }
}

// ---------------------------------------------------------------------------
extern "C" void kernel_launch(void* const* d_in, const int* in_sizes, int n_in,
                              void* d_out, int out_size)
{
    const float* q  = (const float*)d_in[0];
    const float* k  = (const float*)d_in[1];
    const float* v  = (const float*)d_in[2];
    const int* mask = (const int*)d_in[3];
    const float* Wq = (const float*)d_in[4];
    const float* bq = (const float*)d_in[5];
    const float* Wk = (const float*)d_in[6];
    const float* bk = (const float*)d_in[7];
    const float* Wv = (const float*)d_in[8];
    const float* bv = (const float*)d_in[9];
    const float* Wo = (const float*)d_in[10];
    const float* bo = (const float*)d_in[11];
    float* out = (float*)d_out;

    cudaFuncSetAttribute(attn_mma, cudaFuncAttributeMaxDynamicSharedMemorySize, SMEM_ATTN);

    dim3 g1((B_ * S_) / 128, H_ / 2, 3);
    proj_mma<<<g1, 256>>>(q, k, v, Wq, Wk, Wv, bq, bk, bv);

    dim3 g2(S_ / 128, B_ * H_);
    attn_mma<<<g2, 256, SMEM_ATTN>>>(mask);

    dim3 g3((B_ * S_) / 128, DOUT_ / 128);
    out_mma<<<g3, 256>>>(Wo, bo, out);
}

// round 13
// speedup vs baseline: 1.8487x; 1.3370x over previous
#include <cuda_runtime.h>
#include <cuda_fp16.h>
#include <cstdint>

#define B_ 4
#define S_ 2048
#define D_ 1024
#define H_ 16
#define DK_ 64
#define DV_ 64
#define DOUT_ 1024

// Scratch, fp16: qh/kh/vh (b,h,s,e); qh pre-scaled by 0.125*log2e.
// cat stored as packed half2 words: [b*S+s][H*DV/2].
__device__ __half  g_qh[(size_t)B_*H_*S_*DK_];
__device__ __half  g_kh[(size_t)B_*H_*S_*DK_];
__device__ __half  g_vh[(size_t)B_*H_*S_*DV_];
__device__ uint32_t g_cat32[(size_t)B_*S_*(H_*DV_/2)];

// fp16 pre-converted inputs/weights.
__device__ uint32_t g_x16[(size_t)3*B_*S_*D_/2];         // q,k,v as half2 words
__device__ __half   g_wt16[(size_t)3*H_*DK_*D_];         // Wq/Wk/Wv transposed [z][h][e][d]
__device__ __half   g_wot16[(size_t)DOUT_*DOUT_];        // Wo transposed [n][k]

// ---------------------------------------------------------------------------
// PTX helpers
// ---------------------------------------------------------------------------
__device__ __forceinline__ uint32_t packh2(float lo, float hi) {
    uint32_t u;
    asm("cvt.rn.f16x2.f32 %0, %1, %2;" : "=r"(u) : "f"(hi), "f"(lo));
    return u;
}

__device__ __forceinline__ void mma_f16(float* d, const uint32_t* a,
                                        uint32_t b0, uint32_t b1) {
    asm volatile(
        "mma.sync.aligned.m16n8k16.row.col.f32.f16.f16.f32 "
        "{%0,%1,%2,%3}, {%4,%5,%6,%7}, {%8,%9}, {%0,%1,%2,%3};\n"
        : "+f"(d[0]), "+f"(d[1]), "+f"(d[2]), "+f"(d[3])
        : "r"(a[0]), "r"(a[1]), "r"(a[2]), "r"(a[3]), "r"(b0), "r"(b1));
}

__device__ __forceinline__ void cpa16(uint32_t dst, const void* src) {
    asm volatile("cp.async.cg.shared.global [%0], [%1], 16;\n" :: "r"(dst), "l"(src));
}
__device__ __forceinline__ void cpa_commit() {
    asm volatile("cp.async.commit_group;\n");
}
template <int N>
__device__ __forceinline__ void cpa_wait() {
    asm volatile("cp.async.wait_group %0;\n" :: "n"(N));
}

#define QSCALE (0.125f * 1.4426950408889634f)

// ---------------------------------------------------------------------------
// Prep 1: q/k/v fp32 -> fp16 (half2 words), same layout.
// ---------------------------------------------------------------------------
__global__ __launch_bounds__(256) void prep_x(
    const float* __restrict__ q, const float* __restrict__ k, const float* __restrict__ v)
{
    const int z = blockIdx.y;
    const float* s = (z == 0) ? q : (z == 1) ? k : v;
    uint32_t* d = g_x16 + (size_t)z * (B_ * S_ * D_ / 2);
    const size_t i = ((size_t)blockIdx.x * 256 + threadIdx.x) * 8;
    float4 v0 = *(const float4*)(s + i);
    float4 v1 = *(const float4*)(s + i + 4);
    uint4 u;
    u.x = packh2(v0.x, v0.y);
    u.y = packh2(v0.z, v0.w);
    u.z = packh2(v1.x, v1.y);
    u.w = packh2(v1.z, v1.w);
    *(uint4*)(d + i / 2) = u;
}

// ---------------------------------------------------------------------------
// Prep 2: weight transpose to fp16.  z<3: Wq/Wk/Wv [h][d][e] -> [z][h][e][d];
// z==3: Wo [k][n] -> [n][k].  32x32 tiles via smem.
// ---------------------------------------------------------------------------
__global__ __launch_bounds__(256) void prep_wt(
    const float* __restrict__ Wq, const float* __restrict__ Wk,
    const float* __restrict__ Wv, const float* __restrict__ Wo)
{
    __shared__ float ts[32][33];
    const int z = blockIdx.z;
    const int tid = threadIdx.x;
    const int r = tid >> 5, c = tid & 31;

    const float* in;
    __half* out;
    int istride, ostride;
    if (z < 3) {
        const float* W = (z == 0) ? Wq : (z == 1) ? Wk : Wv;
        const int h = blockIdx.y >> 1, et = blockIdx.y & 1;
        in  = W + ((size_t)h * D_ + blockIdx.x * 32) * DK_ + et * 32;
        out = g_wt16 + (size_t)z * (H_ * DK_ * D_)
              + ((size_t)h * DK_ + et * 32) * D_ + blockIdx.x * 32;
        istride = DK_; ostride = D_;
    } else {
        in  = Wo + (size_t)(blockIdx.x * 32) * DOUT_ + blockIdx.y * 32;
        out = g_wot16 + (size_t)(blockIdx.y * 32) * DOUT_ + blockIdx.x * 32;
        istride = DOUT_; ostride = DOUT_;
    }

#pragma unroll
    for (int i = 0; i < 4; ++i)
        ts[r + 8 * i][c] = in[(size_t)(r + 8 * i) * istride + c];
    __syncthreads();
#pragma unroll
    for (int i = 0; i < 4; ++i)
        out[(size_t)(r + 8 * i) * ostride + c] = __float2half_rn(ts[c][r + 8 * i]);
}

// ---------------------------------------------------------------------------
// fp16 GEMM tiles: A 128 rows x 16 halves (8 words + 4 pad = APW 12),
// B (transposed weights) identical layout.  Bank audit: (12g+t) mod 32
// spans all 32 banks across the warp -> conflict-free fragment loads.
// ---------------------------------------------------------------------------
#define APW 12

// ---------------------------------------------------------------------------
// Kernel 1: per-head projections, all-fp16 operands, BK=16, R12 pipeline.
// ---------------------------------------------------------------------------
__global__ __launch_bounds__(256, 2) void proj_mma(
    const float* __restrict__ bq, const float* __restrict__ bk, const float* __restrict__ bv)
{
    const int z = blockIdx.z;
    const float* bias = (z == 0) ? bq : (z == 1) ? bk : bv;
    const float osc   = (z == 0) ? QSCALE : 1.0f;
    __half* Out       = (z == 0) ? g_qh : (z == 1) ? g_kh : g_vh;

    const int h0 = blockIdx.y * 2;
    const int m0 = blockIdx.x * 128;
    const int b  = m0 >> 11;
    const int s0 = m0 & (S_ - 1);

    const uint32_t* Xw = g_x16 + (size_t)z * (B_ * S_ * D_ / 2) + (size_t)m0 * (D_ / 2);
    const __half* Wt = g_wt16 + (size_t)z * (H_ * DK_ * D_) + (size_t)(h0 * 64) * D_;

    __shared__ uint32_t As[2][128 * APW];
    __shared__ uint32_t Bsm[2][128 * APW];

    const int tid = threadIdx.x;
    const int wid = tid >> 5, lane = tid & 31;
    const int wm = wid >> 2, wn = wid & 3;
    const int g = lane >> 2, t = lane & 3;

    const int lrow = tid >> 1, lw = (tid & 1) * 4;   // 128 rows x 2 segs (8 halves)

    uint32_t aDst[2], bDst[2];
    aDst[0] = (uint32_t)__cvta_generic_to_shared(&As[0][lrow * APW + lw]);
    aDst[1] = (uint32_t)__cvta_generic_to_shared(&As[1][lrow * APW + lw]);
    bDst[0] = (uint32_t)__cvta_generic_to_shared(&Bsm[0][lrow * APW + lw]);
    bDst[1] = (uint32_t)__cvta_generic_to_shared(&Bsm[1][lrow * APW + lw]);

    float acc[4][4][4] = {};

    {
        cpa16(aDst[0], Xw + (size_t)lrow * (D_ / 2) + lw);
        cpa16(bDst[0], Wt + (size_t)lrow * D_ + lw * 2);
        cpa_commit();
    }

    const int NT = D_ / 16;
#pragma unroll 1
    for (int it = 0; it < NT; ++it) {
        if (it + 1 < NT) {
            const int bi = (it + 1) & 1;
            cpa16(aDst[bi], Xw + (size_t)lrow * (D_ / 2) + (it + 1) * 8 + lw);
            cpa16(bDst[bi], Wt + (size_t)lrow * D_ + (it + 1) * 16 + lw * 2);
            cpa_commit();
            cpa_wait<1>();
        } else {
            cpa_wait<0>();
        }
        __syncthreads();

        const uint32_t* Ab = As[it & 1];
        const uint32_t* Bb = Bsm[it & 1];
        uint32_t a[4][4];
#pragma unroll
        for (int mf = 0; mf < 4; ++mf) {
            const int m = wm * 64 + mf * 16;
            a[mf][0] = Ab[(m + g)     * APW + t];
            a[mf][1] = Ab[(m + g + 8) * APW + t];
            a[mf][2] = Ab[(m + g)     * APW + t + 4];
            a[mf][3] = Ab[(m + g + 8) * APW + t + 4];
        }
#pragma unroll
        for (int nf = 0; nf < 4; ++nf) {
            const int n = wn * 32 + nf * 8 + g;
            const uint32_t b0 = Bb[n * APW + t];
            const uint32_t b1 = Bb[n * APW + t + 4];
#pragma unroll
            for (int mf = 0; mf < 4; ++mf)
                mma_f16(acc[mf][nf], a[mf], b0, b1);
        }
        __syncthreads();
    }

#pragma unroll
    for (int nf = 0; nf < 4; ++nf) {
        const int c = wn * 32 + nf * 8 + t * 2;
        const int h = h0 + (c >> 6);
        const int e = c & 63;
        const float b0v = bias[h * DK_ + e];
        const float b1v = bias[h * DK_ + e + 1];
        __half* Ob = Out + ((size_t)(b * H_ + h) * S_ + s0) * DK_ + e;
#pragma unroll
        for (int mf = 0; mf < 4; ++mf) {
            const int r = wm * 64 + mf * 16 + g;
            *(uint32_t*)(Ob + (size_t)r * DK_) =
                packh2((acc[mf][nf][0] + b0v) * osc, (acc[mf][nf][1] + b1v) * osc);
            *(uint32_t*)(Ob + (size_t)(r + 8) * DK_) =
                packh2((acc[mf][nf][2] + b0v) * osc, (acc[mf][nf][3] + b1v) * osc);
        }
    }
}

// ---------------------------------------------------------------------------
// Kernel 2: fp16 tensor-core flash attention (unchanged from R12).
// ---------------------------------------------------------------------------
#define QPW 36
#define KBUFW (64 * QPW)
#define SM_K 4608
#define SM_V (SM_K + 2 * KBUFW)
#define SM_M (SM_V + 2 * KBUFW)
#define SMEM_ATTN ((SM_M + 128) * 4)

__global__ __launch_bounds__(256, 2) void attn_mma(const int* __restrict__ mask)
{
    extern __shared__ uint32_t smw[];
    uint32_t* Qs = smw;
    int*      Msall = (int*)(smw + SM_M);

    const int bh = blockIdx.y;
    const int b = bh >> 4, h = bh & 15;
    const int q0 = blockIdx.x * 128;

    const __half* Qg = g_qh + ((size_t)bh * S_ + q0) * DK_;
    const __half* Kg = g_kh + (size_t)bh * S_ * DK_;
    const __half* Vg = g_vh + (size_t)bh * S_ * DK_;
    const int* mk = mask + (size_t)b * S_;

    const int tid = threadIdx.x;
    const int w = tid >> 5, lane = tid & 31;
    const int g = lane >> 2, t = lane & 3;

    const uint32_t* Qg32 = (const uint32_t*)Qg;
    for (int i = tid; i < 1024; i += 256) {
        const int row = i >> 3, ws = (i & 7) * 4;
        *(uint4*)(&Qs[row * QPW + ws]) = *(const uint4*)(Qg32 + row * 32 + ws);
    }

    {
#pragma unroll
        for (int j = 0; j < 2; ++j) {
            const int idx = tid + j * 256;
            const int row = idx >> 3, hc = (idx & 7) * 8;
            cpa16((uint32_t)__cvta_generic_to_shared(smw + SM_K + row * QPW + hc / 2),
                  Kg + (size_t)row * DK_ + hc);
            cpa16((uint32_t)__cvta_generic_to_shared(smw + SM_V + row * QPW + hc / 2),
                  Vg + (size_t)row * DK_ + hc);
        }
        if (tid < 16)
            cpa16((uint32_t)__cvta_generic_to_shared((uint32_t*)(Msall) + tid * 4),
                  mk + tid * 4);
        cpa_commit();
    }

    float oacc[8][4] = {};
    float mold0 = -1e30f, mold1 = -1e30f;
    float lp0 = 0.0f, lp1 = 0.0f;

    const uint32_t* qbase = Qs + (w * 16 + g) * QPW;

    const int NCH = S_ / 64;
#pragma unroll 1
    for (int chunk = 0; chunk < NCH; ++chunk) {
        const int bi = chunk & 1;

        if (chunk + 1 < NCH) {
            const int kc = (chunk + 1) * 64;
            const int bo2 = bi ^ 1;
#pragma unroll
            for (int j = 0; j < 2; ++j) {
                const int idx = tid + j * 256;
                const int row = idx >> 3, hc = (idx & 7) * 8;
                cpa16((uint32_t)__cvta_generic_to_shared(
                          smw + SM_K + bo2 * KBUFW + row * QPW + hc / 2),
                      Kg + (size_t)(kc + row) * DK_ + hc);
                cpa16((uint32_t)__cvta_generic_to_shared(
                          smw + SM_V + bo2 * KBUFW + row * QPW + hc / 2),
                      Vg + (size_t)(kc + row) * DK_ + hc);
            }
            if (tid < 16)
                cpa16((uint32_t)__cvta_generic_to_shared(
                          (uint32_t*)(Msall) + bo2 * 64 + tid * 4),
                      mk + kc + tid * 4);
            cpa_commit();
            cpa_wait<1>();
        } else {
            cpa_wait<0>();
        }
        __syncthreads();

        const uint32_t* Kw = smw + SM_K + bi * KBUFW;
        const unsigned short* Vh = (const unsigned short*)(smw + SM_V + bi * KBUFW);
        const int* Mb = Msall + bi * 64;

        float sc[8][4] = {};
#pragma unroll
        for (int kb = 0; kb < 4; ++kb) {
            uint32_t a[4];
            const uint32_t* qr = qbase + kb * 8 + t;
            a[0] = qr[0];
            a[1] = qr[8 * QPW];
            a[2] = qr[4];
            a[3] = qr[8 * QPW + 4];
#pragma unroll
            for (int nf = 0; nf < 8; ++nf) {
                const uint32_t* kr = Kw + (nf * 8 + g) * QPW + kb * 8 + t;
                mma_f16(sc[nf], a, kr[0], kr[4]);
            }
        }

        float tm0 = -1e30f, tm1 = -1e30f;
#pragma unroll
        for (int nf = 0; nf < 8; ++nf) {
            const int ma = Mb[nf * 8 + 2 * t];
            const int mb = Mb[nf * 8 + 2 * t + 1];
            if (!ma) { sc[nf][0] = -1e30f; sc[nf][2] = -1e30f; }
            if (!mb) { sc[nf][1] = -1e30f; sc[nf][3] = -1e30f; }
            tm0 = fmaxf(tm0, fmaxf(sc[nf][0], sc[nf][1]));
            tm1 = fmaxf(tm1, fmaxf(sc[nf][2], sc[nf][3]));
        }
        tm0 = fmaxf(tm0, __shfl_xor_sync(0xffffffffu, tm0, 1));
        tm0 = fmaxf(tm0, __shfl_xor_sync(0xffffffffu, tm0, 2));
        tm1 = fmaxf(tm1, __shfl_xor_sync(0xffffffffu, tm1, 1));
        tm1 = fmaxf(tm1, __shfl_xor_sync(0xffffffffu, tm1, 2));

        const float mn0 = fmaxf(mold0, tm0);
        const float mn1 = fmaxf(mold1, tm1);
        const float f0 = exp2f(mold0 - mn0);
        const float f1 = exp2f(mold1 - mn1);
        mold0 = mn0; mold1 = mn1;

        float cs0 = 0.0f, cs1 = 0.0f;
#pragma unroll
        for (int nf = 0; nf < 8; ++nf) {
            sc[nf][0] = exp2f(sc[nf][0] - mn0);
            sc[nf][1] = exp2f(sc[nf][1] - mn0);
            sc[nf][2] = exp2f(sc[nf][2] - mn1);
            sc[nf][3] = exp2f(sc[nf][3] - mn1);
            cs0 += sc[nf][0] + sc[nf][1];
            cs1 += sc[nf][2] + sc[nf][3];
        }
        lp0 = lp0 * f0 + cs0;
        lp1 = lp1 * f1 + cs1;

#pragma unroll
        for (int nf = 0; nf < 8; ++nf) {
            oacc[nf][0] *= f0; oacc[nf][1] *= f0;
            oacc[nf][2] *= f1; oacc[nf][3] *= f1;
        }

#pragma unroll
        for (int kb = 0; kb < 4; ++kb) {
            uint32_t a[4];
            a[0] = packh2(sc[2 * kb][0],     sc[2 * kb][1]);
            a[1] = packh2(sc[2 * kb][2],     sc[2 * kb][3]);
            a[2] = packh2(sc[2 * kb + 1][0], sc[2 * kb + 1][1]);
            a[3] = packh2(sc[2 * kb + 1][2], sc[2 * kb + 1][3]);
            const int r0 = kb * 16 + 2 * t;
#pragma unroll
            for (int nf = 0; nf < 8; ++nf) {
                const int n = nf * 8 + g;
                uint32_t b0 = (uint32_t)Vh[r0 * 72 + n] |
                              ((uint32_t)Vh[(r0 + 1) * 72 + n] << 16);
                uint32_t b1 = (uint32_t)Vh[(r0 + 8) * 72 + n] |
                              ((uint32_t)Vh[(r0 + 9) * 72 + n] << 16);
                mma_f16(oacc[nf], a, b0, b1);
            }
        }
        __syncthreads();
    }

    lp0 += __shfl_xor_sync(0xffffffffu, lp0, 1);
    lp0 += __shfl_xor_sync(0xffffffffu, lp0, 2);
    lp1 += __shfl_xor_sync(0xffffffffu, lp1, 1);
    lp1 += __shfl_xor_sync(0xffffffffu, lp1, 2);
    const float inv0 = 1.0f / lp0;
    const float inv1 = 1.0f / lp1;

    const int r0 = q0 + w * 16 + g;
    uint32_t* cat0 = g_cat32 + ((size_t)b * S_ + r0) * 512 + h * 32;
    uint32_t* cat1 = cat0 + (size_t)8 * 512;
#pragma unroll
    for (int nf = 0; nf < 8; ++nf) {
        const int cw = nf * 4 + t;
        cat0[cw] = packh2(oacc[nf][0] * inv0, oacc[nf][1] * inv0);
        cat1[cw] = packh2(oacc[nf][2] * inv1, oacc[nf][3] * inv1);
    }
}

// ---------------------------------------------------------------------------
// Kernel 3: output projection, all-fp16 operands (cat + transposed Wo).
// ---------------------------------------------------------------------------
__global__ __launch_bounds__(256, 2) void out_mma(
    const float* __restrict__ bo, float* __restrict__ out)
{
    const int m0 = blockIdx.x * 128;
    const int n0 = blockIdx.y * 128;

    const uint32_t* Aw = g_cat32 + (size_t)m0 * 512;
    const __half* Wt = g_wot16 + (size_t)n0 * DOUT_;

    __shared__ uint32_t As[2][128 * APW];
    __shared__ uint32_t Bsm[2][128 * APW];

    const int tid = threadIdx.x;
    const int wid = tid >> 5, lane = tid & 31;
    const int wm = wid >> 2, wn = wid & 3;
    const int g = lane >> 2, t = lane & 3;

    const int lrow = tid >> 1, lw = (tid & 1) * 4;

    uint32_t aDst[2], bDst[2];
    aDst[0] = (uint32_t)__cvta_generic_to_shared(&As[0][lrow * APW + lw]);
    aDst[1] = (uint32_t)__cvta_generic_to_shared(&As[1][lrow * APW + lw]);
    bDst[0] = (uint32_t)__cvta_generic_to_shared(&Bsm[0][lrow * APW + lw]);
    bDst[1] = (uint32_t)__cvta_generic_to_shared(&Bsm[1][lrow * APW + lw]);

    float acc[4][4][4] = {};

    {
        cpa16(aDst[0], Aw + (size_t)lrow * 512 + lw);
        cpa16(bDst[0], Wt + (size_t)lrow * DOUT_ + lw * 2);
        cpa_commit();
    }

    const int NT = DOUT_ / 16;
#pragma unroll 1
    for (int it = 0; it < NT; ++it) {
        if (it + 1 < NT) {
            const int bi = (it + 1) & 1;
            cpa16(aDst[bi], Aw + (size_t)lrow * 512 + (it + 1) * 8 + lw);
            cpa16(bDst[bi], Wt + (size_t)lrow * DOUT_ + (it + 1) * 16 + lw * 2);
            cpa_commit();
            cpa_wait<1>();
        } else {
            cpa_wait<0>();
        }
        __syncthreads();

        const uint32_t* Ab = As[it & 1];
        const uint32_t* Bb = Bsm[it & 1];
        uint32_t a[4][4];
#pragma unroll
        for (int mf = 0; mf < 4; ++mf) {
            const int m = wm * 64 + mf * 16;
            a[mf][0] = Ab[(m + g)     * APW + t];
            a[mf][1] = Ab[(m + g + 8) * APW + t];
            a[mf][2] = Ab[(m + g)     * APW + t + 4];
            a[mf][3] = Ab[(m + g + 8) * APW + t + 4];
        }
#pragma unroll
        for (int nf = 0; nf < 4; ++nf) {
            const int n = wn * 32 + nf * 8 + g;
            const uint32_t b0 = Bb[n * APW + t];
            const uint32_t b1 = Bb[n * APW + t + 4];
#pragma unroll
            for (int mf = 0; mf < 4; ++mf)
                mma_f16(acc[mf][nf], a[mf], b0, b1);
        }
        __syncthreads();
    }

#pragma unroll
    for (int nf = 0; nf < 4; ++nf) {
        const int c = n0 + wn * 32 + nf * 8 + t * 2;
        const float b0v = bo[c], b1v = bo[c + 1];
#pragma unroll
        for (int mf = 0; mf < 4; ++mf) {
            const int r = m0 + wm * 64 + mf * 16 + g;
            *(float2*)(out + (size_t)r * DOUT_ + c) =
                make_float2(acc[mf][nf][0] + b0v, acc[mf][nf][1] + b1v);
            *(float2*)(out + (size_t)(r + 8) * DOUT_ + c) =
                make_float2(acc[mf][nf][2] + b0v, acc[mf][nf][3] + b1v);
        }
    }
}

// ---------------------------------------------------------------------------
extern "C" void kernel_launch(void* const* d_in, const int* in_sizes, int n_in,
                              void* d_out, int out_size)
{
    const float* q  = (const float*)d_in[0];
    const float* k  = (const float*)d_in[1];
    const float* v  = (const float*)d_in[2];
    const int* mask = (const int*)d_in[3];
    const float* Wq = (const float*)d_in[4];
    const float* bq = (const float*)d_in[5];
    const float* Wk = (const float*)d_in[6];
    const float* bk = (const float*)d_in[7];
    const float* Wv = (const float*)d_in[8];
    const float* bv = (const float*)d_in[9];
    const float* Wo = (const float*)d_in[10];
    const float* bo = (const float*)d_in[11];
    float* out = (float*)d_out;

    cudaFuncSetAttribute(attn_mma, cudaFuncAttributeMaxDynamicSharedMemorySize, SMEM_ATTN);

    dim3 gp1((B_ * S_ * D_) / (256 * 8), 3);
    prep_x<<<gp1, 256>>>(q, k, v);
    dim3 gp2(32, 32, 4);
    prep_wt<<<gp2, 256>>>(Wq, Wk, Wv, Wo);

    dim3 g1((B_ * S_) / 128, H_ / 2, 3);
    proj_mma<<<g1, 256>>>(bq, bk, bv);

    dim3 g2(S_ / 128, B_ * H_);
    attn_mma<<<g2, 256, SMEM_ATTN>>>(mask);

    dim3 g3((B_ * S_) / 128, DOUT_ / 128);
    out_mma<<<g3, 256>>>(bo, out);
}

// round 14
// speedup vs baseline: 1.9867x; 1.0746x over previous
#include <cuda_runtime.h>
#include <cuda_fp16.h>
#include <cstdint>

#define B_ 4
#define S_ 2048
#define D_ 1024
#define H_ 16
#define DK_ 64
#define DV_ 64
#define DOUT_ 1024

// Scratch, fp16: qh/kh (b,h,s,e); qh pre-scaled by 0.125*log2e.
// V stored TRANSPOSED: g_vht (b,h,e,s) so attention P@V B-frags are word loads.
// cat stored as packed half2 words: [b*S+s][H*DV/2].
__device__ __half  g_qh[(size_t)B_*H_*S_*DK_];
__device__ __half  g_kh[(size_t)B_*H_*S_*DK_];
__device__ __half  g_vht[(size_t)B_*H_*DV_*S_];
__device__ uint32_t g_cat32[(size_t)B_*S_*(H_*DV_/2)];

// fp16 pre-converted inputs/weights.
__device__ uint32_t g_x16[(size_t)3*B_*S_*D_/2];         // q,k,v as half2 words
__device__ __half   g_wt16[(size_t)3*H_*DK_*D_];         // Wq/Wk/Wv transposed [z][h][e][d]
__device__ __half   g_wot16[(size_t)DOUT_*DOUT_];        // Wo transposed [n][k]

// ---------------------------------------------------------------------------
// PTX helpers
// ---------------------------------------------------------------------------
__device__ __forceinline__ uint32_t packh2(float lo, float hi) {
    uint32_t u;
    asm("cvt.rn.f16x2.f32 %0, %1, %2;" : "=r"(u) : "f"(hi), "f"(lo));
    return u;
}

__device__ __forceinline__ void mma_f16(float* d, const uint32_t* a,
                                        uint32_t b0, uint32_t b1) {
    asm volatile(
        "mma.sync.aligned.m16n8k16.row.col.f32.f16.f16.f32 "
        "{%0,%1,%2,%3}, {%4,%5,%6,%7}, {%8,%9}, {%0,%1,%2,%3};\n"
        : "+f"(d[0]), "+f"(d[1]), "+f"(d[2]), "+f"(d[3])
        : "r"(a[0]), "r"(a[1]), "r"(a[2]), "r"(a[3]), "r"(b0), "r"(b1));
}

__device__ __forceinline__ void cpa16(uint32_t dst, const void* src) {
    asm volatile("cp.async.cg.shared.global [%0], [%1], 16;\n" :: "r"(dst), "l"(src));
}
__device__ __forceinline__ void cpa_commit() {
    asm volatile("cp.async.commit_group;\n");
}
template <int N>
__device__ __forceinline__ void cpa_wait() {
    asm volatile("cp.async.wait_group %0;\n" :: "n"(N));
}

#define QSCALE (0.125f * 1.4426950408889634f)

// ---------------------------------------------------------------------------
// Prep 1: q/k/v fp32 -> fp16 (half2 words), same layout.
// ---------------------------------------------------------------------------
__global__ __launch_bounds__(256) void prep_x(
    const float* __restrict__ q, const float* __restrict__ k, const float* __restrict__ v)
{
    const int z = blockIdx.y;
    const float* s = (z == 0) ? q : (z == 1) ? k : v;
    uint32_t* d = g_x16 + (size_t)z * (B_ * S_ * D_ / 2);
    const size_t i = ((size_t)blockIdx.x * 256 + threadIdx.x) * 8;
    float4 v0 = *(const float4*)(s + i);
    float4 v1 = *(const float4*)(s + i + 4);
    uint4 u;
    u.x = packh2(v0.x, v0.y);
    u.y = packh2(v0.z, v0.w);
    u.z = packh2(v1.x, v1.y);
    u.w = packh2(v1.z, v1.w);
    *(uint4*)(d + i / 2) = u;
}

// ---------------------------------------------------------------------------
// Prep 2: weight transpose to fp16.  z<3: Wq/Wk/Wv [h][d][e] -> [z][h][e][d];
// z==3: Wo [k][n] -> [n][k].  32x32 tiles via smem.
// ---------------------------------------------------------------------------
__global__ __launch_bounds__(256) void prep_wt(
    const float* __restrict__ Wq, const float* __restrict__ Wk,
    const float* __restrict__ Wv, const float* __restrict__ Wo)
{
    __shared__ float ts[32][33];
    const int z = blockIdx.z;
    const int tid = threadIdx.x;
    const int r = tid >> 5, c = tid & 31;

    const float* in;
    __half* out;
    int istride, ostride;
    if (z < 3) {
        const float* W = (z == 0) ? Wq : (z == 1) ? Wk : Wv;
        const int h = blockIdx.y >> 1, et = blockIdx.y & 1;
        in  = W + ((size_t)h * D_ + blockIdx.x * 32) * DK_ + et * 32;
        out = g_wt16 + (size_t)z * (H_ * DK_ * D_)
              + ((size_t)h * DK_ + et * 32) * D_ + blockIdx.x * 32;
        istride = DK_; ostride = D_;
    } else {
        in  = Wo + (size_t)(blockIdx.x * 32) * DOUT_ + blockIdx.y * 32;
        out = g_wot16 + (size_t)(blockIdx.y * 32) * DOUT_ + blockIdx.x * 32;
        istride = DOUT_; ostride = DOUT_;
    }

#pragma unroll
    for (int i = 0; i < 4; ++i)
        ts[r + 8 * i][c] = in[(size_t)(r + 8 * i) * istride + c];
    __syncthreads();
#pragma unroll
    for (int i = 0; i < 4; ++i)
        out[(size_t)(r + 8 * i) * ostride + c] = __float2half_rn(ts[c][r + 8 * i]);
}

// fp16 GEMM tiles: 128 rows x 16 halves (8 words + 4 pad).
#define APW 12

// ---------------------------------------------------------------------------
// Kernel 1: per-head projections, all-fp16 operands, BK=16, R12 pipeline.
// z==2 (V) epilogue stores TRANSPOSED (b,h,e,s).
// ---------------------------------------------------------------------------
__global__ __launch_bounds__(256, 2) void proj_mma(
    const float* __restrict__ bq, const float* __restrict__ bk, const float* __restrict__ bv)
{
    const int z = blockIdx.z;
    const float* bias = (z == 0) ? bq : (z == 1) ? bk : bv;
    const float osc   = (z == 0) ? QSCALE : 1.0f;

    const int h0 = blockIdx.y * 2;
    const int m0 = blockIdx.x * 128;
    const int b  = m0 >> 11;
    const int s0 = m0 & (S_ - 1);

    const uint32_t* Xw = g_x16 + (size_t)z * (B_ * S_ * D_ / 2) + (size_t)m0 * (D_ / 2);
    const __half* Wt = g_wt16 + (size_t)z * (H_ * DK_ * D_) + (size_t)(h0 * 64) * D_;

    __shared__ uint32_t As[2][128 * APW];
    __shared__ uint32_t Bsm[2][128 * APW];

    const int tid = threadIdx.x;
    const int wid = tid >> 5, lane = tid & 31;
    const int wm = wid >> 2, wn = wid & 3;
    const int g = lane >> 2, t = lane & 3;

    const int lrow = tid >> 1, lw = (tid & 1) * 4;

    uint32_t aDst[2], bDst[2];
    aDst[0] = (uint32_t)__cvta_generic_to_shared(&As[0][lrow * APW + lw]);
    aDst[1] = (uint32_t)__cvta_generic_to_shared(&As[1][lrow * APW + lw]);
    bDst[0] = (uint32_t)__cvta_generic_to_shared(&Bsm[0][lrow * APW + lw]);
    bDst[1] = (uint32_t)__cvta_generic_to_shared(&Bsm[1][lrow * APW + lw]);

    float acc[4][4][4] = {};

    {
        cpa16(aDst[0], Xw + (size_t)lrow * (D_ / 2) + lw);
        cpa16(bDst[0], Wt + (size_t)lrow * D_ + lw * 2);
        cpa_commit();
    }

    const int NT = D_ / 16;
#pragma unroll 1
    for (int it = 0; it < NT; ++it) {
        if (it + 1 < NT) {
            const int bi = (it + 1) & 1;
            cpa16(aDst[bi], Xw + (size_t)lrow * (D_ / 2) + (it + 1) * 8 + lw);
            cpa16(bDst[bi], Wt + (size_t)lrow * D_ + (it + 1) * 16 + lw * 2);
            cpa_commit();
            cpa_wait<1>();
        } else {
            cpa_wait<0>();
        }
        __syncthreads();

        const uint32_t* Ab = As[it & 1];
        const uint32_t* Bb = Bsm[it & 1];
        uint32_t a[4][4];
#pragma unroll
        for (int mf = 0; mf < 4; ++mf) {
            const int m = wm * 64 + mf * 16;
            a[mf][0] = Ab[(m + g)     * APW + t];
            a[mf][1] = Ab[(m + g + 8) * APW + t];
            a[mf][2] = Ab[(m + g)     * APW + t + 4];
            a[mf][3] = Ab[(m + g + 8) * APW + t + 4];
        }
#pragma unroll
        for (int nf = 0; nf < 4; ++nf) {
            const int n = wn * 32 + nf * 8 + g;
            const uint32_t b0 = Bb[n * APW + t];
            const uint32_t b1 = Bb[n * APW + t + 4];
#pragma unroll
            for (int mf = 0; mf < 4; ++mf)
                mma_f16(acc[mf][nf], a[mf], b0, b1);
        }
        __syncthreads();
    }

    if (z == 2) {
        // V: transposed store (b,h,e,s)
#pragma unroll
        for (int nf = 0; nf < 4; ++nf) {
            const int c = wn * 32 + nf * 8 + t * 2;
            const int h = h0 + (c >> 6);
            const int e = c & 63;
            const float b0v = bias[h * DK_ + e];
            const float b1v = bias[h * DK_ + e + 1];
            __half* O0 = g_vht + ((size_t)(b * H_ + h) * DK_ + e) * S_ + s0;
            __half* O1 = O0 + S_;
#pragma unroll
            for (int mf = 0; mf < 4; ++mf) {
                const int r = wm * 64 + mf * 16 + g;
                O0[r]     = __float2half_rn(acc[mf][nf][0] + b0v);
                O1[r]     = __float2half_rn(acc[mf][nf][1] + b1v);
                O0[r + 8] = __float2half_rn(acc[mf][nf][2] + b0v);
                O1[r + 8] = __float2half_rn(acc[mf][nf][3] + b1v);
            }
        }
    } else {
        __half* Out = (z == 0) ? g_qh : g_kh;
#pragma unroll
        for (int nf = 0; nf < 4; ++nf) {
            const int c = wn * 32 + nf * 8 + t * 2;
            const int h = h0 + (c >> 6);
            const int e = c & 63;
            const float b0v = bias[h * DK_ + e];
            const float b1v = bias[h * DK_ + e + 1];
            __half* Ob = Out + ((size_t)(b * H_ + h) * S_ + s0) * DK_ + e;
#pragma unroll
            for (int mf = 0; mf < 4; ++mf) {
                const int r = wm * 64 + mf * 16 + g;
                *(uint32_t*)(Ob + (size_t)r * DK_) =
                    packh2((acc[mf][nf][0] + b0v) * osc, (acc[mf][nf][1] + b1v) * osc);
                *(uint32_t*)(Ob + (size_t)(r + 8) * DK_) =
                    packh2((acc[mf][nf][2] + b0v) * osc, (acc[mf][nf][3] + b1v) * osc);
            }
        }
    }
}

// ---------------------------------------------------------------------------
// Kernel 2: fp16 flash attention.  V arrives transposed -> PV B-frags are
// word loads (same pattern as QK's K loads).  R12 pipeline otherwise.
// ---------------------------------------------------------------------------
#define QPW 36
#define KBUFW (64 * QPW)
#define SM_K 4608
#define SM_V (SM_K + 2 * KBUFW)
#define SM_M (SM_V + 2 * KBUFW)
#define SMEM_ATTN ((SM_M + 128) * 4)

__global__ __launch_bounds__(256, 2) void attn_mma(const int* __restrict__ mask)
{
    extern __shared__ uint32_t smw[];
    uint32_t* Qs = smw;
    int*      Msall = (int*)(smw + SM_M);

    const int bh = blockIdx.y;
    const int b = bh >> 4, h = bh & 15;
    const int q0 = blockIdx.x * 128;

    const __half* Qg = g_qh + ((size_t)bh * S_ + q0) * DK_;
    const __half* Kg = g_kh + (size_t)bh * S_ * DK_;
    const __half* Vtg = g_vht + (size_t)bh * DV_ * S_;
    const int* mk = mask + (size_t)b * S_;

    const int tid = threadIdx.x;
    const int w = tid >> 5, lane = tid & 31;
    const int g = lane >> 2, t = lane & 3;

    const uint32_t* Qg32 = (const uint32_t*)Qg;
    for (int i = tid; i < 1024; i += 256) {
        const int row = i >> 3, ws = (i & 7) * 4;
        *(uint4*)(&Qs[row * QPW + ws]) = *(const uint4*)(Qg32 + row * 32 + ws);
    }

    // prologue: chunk 0 -> buffer 0.  K rows = keys; Vt rows = e (both 64x64).
    {
#pragma unroll
        for (int j = 0; j < 2; ++j) {
            const int idx = tid + j * 256;
            const int row = idx >> 3, hc = (idx & 7) * 8;
            cpa16((uint32_t)__cvta_generic_to_shared(smw + SM_K + row * QPW + hc / 2),
                  Kg + (size_t)row * DK_ + hc);
            cpa16((uint32_t)__cvta_generic_to_shared(smw + SM_V + row * QPW + hc / 2),
                  Vtg + (size_t)row * S_ + hc);
        }
        if (tid < 16)
            cpa16((uint32_t)__cvta_generic_to_shared((uint32_t*)(Msall) + tid * 4),
                  mk + tid * 4);
        cpa_commit();
    }

    float oacc[8][4] = {};
    float mold0 = -1e30f, mold1 = -1e30f;
    float lp0 = 0.0f, lp1 = 0.0f;

    const uint32_t* qbase = Qs + (w * 16 + g) * QPW;

    const int NCH = S_ / 64;
#pragma unroll 1
    for (int chunk = 0; chunk < NCH; ++chunk) {
        const int bi = chunk & 1;

        if (chunk + 1 < NCH) {
            const int kc = (chunk + 1) * 64;
            const int bo2 = bi ^ 1;
#pragma unroll
            for (int j = 0; j < 2; ++j) {
                const int idx = tid + j * 256;
                const int row = idx >> 3, hc = (idx & 7) * 8;
                cpa16((uint32_t)__cvta_generic_to_shared(
                          smw + SM_K + bo2 * KBUFW + row * QPW + hc / 2),
                      Kg + (size_t)(kc + row) * DK_ + hc);
                cpa16((uint32_t)__cvta_generic_to_shared(
                          smw + SM_V + bo2 * KBUFW + row * QPW + hc / 2),
                      Vtg + (size_t)row * S_ + kc + hc);
            }
            if (tid < 16)
                cpa16((uint32_t)__cvta_generic_to_shared(
                          (uint32_t*)(Msall) + bo2 * 64 + tid * 4),
                      mk + kc + tid * 4);
            cpa_commit();
            cpa_wait<1>();
        } else {
            cpa_wait<0>();
        }
        __syncthreads();

        const uint32_t* Kw  = smw + SM_K + bi * KBUFW;
        const uint32_t* VtW = smw + SM_V + bi * KBUFW;
        const int* Mb = Msall + bi * 64;

        // --- scores: S = Q @ K^T ---
        float sc[8][4] = {};
#pragma unroll
        for (int kb = 0; kb < 4; ++kb) {
            uint32_t a[4];
            const uint32_t* qr = qbase + kb * 8 + t;
            a[0] = qr[0];
            a[1] = qr[8 * QPW];
            a[2] = qr[4];
            a[3] = qr[8 * QPW + 4];
#pragma unroll
            for (int nf = 0; nf < 8; ++nf) {
                const uint32_t* kr = Kw + (nf * 8 + g) * QPW + kb * 8 + t;
                mma_f16(sc[nf], a, kr[0], kr[4]);
            }
        }

        // --- mask + row max ---
        float tm0 = -1e30f, tm1 = -1e30f;
#pragma unroll
        for (int nf = 0; nf < 8; ++nf) {
            const int ma = Mb[nf * 8 + 2 * t];
            const int mb = Mb[nf * 8 + 2 * t + 1];
            if (!ma) { sc[nf][0] = -1e30f; sc[nf][2] = -1e30f; }
            if (!mb) { sc[nf][1] = -1e30f; sc[nf][3] = -1e30f; }
            tm0 = fmaxf(tm0, fmaxf(sc[nf][0], sc[nf][1]));
            tm1 = fmaxf(tm1, fmaxf(sc[nf][2], sc[nf][3]));
        }
        tm0 = fmaxf(tm0, __shfl_xor_sync(0xffffffffu, tm0, 1));
        tm0 = fmaxf(tm0, __shfl_xor_sync(0xffffffffu, tm0, 2));
        tm1 = fmaxf(tm1, __shfl_xor_sync(0xffffffffu, tm1, 1));
        tm1 = fmaxf(tm1, __shfl_xor_sync(0xffffffffu, tm1, 2));

        const float mn0 = fmaxf(mold0, tm0);
        const float mn1 = fmaxf(mold1, tm1);
        const float f0 = exp2f(mold0 - mn0);
        const float f1 = exp2f(mold1 - mn1);
        mold0 = mn0; mold1 = mn1;

        // --- exp + partial sums ---
        float cs0 = 0.0f, cs1 = 0.0f;
#pragma unroll
        for (int nf = 0; nf < 8; ++nf) {
            sc[nf][0] = exp2f(sc[nf][0] - mn0);
            sc[nf][1] = exp2f(sc[nf][1] - mn0);
            sc[nf][2] = exp2f(sc[nf][2] - mn1);
            sc[nf][3] = exp2f(sc[nf][3] - mn1);
            cs0 += sc[nf][0] + sc[nf][1];
            cs1 += sc[nf][2] + sc[nf][3];
        }
        lp0 = lp0 * f0 + cs0;
        lp1 = lp1 * f1 + cs1;

#pragma unroll
        for (int nf = 0; nf < 8; ++nf) {
            oacc[nf][0] *= f0; oacc[nf][1] *= f0;
            oacc[nf][2] *= f1; oacc[nf][3] *= f1;
        }

        // --- O += P @ V via V^T word loads (same pattern as K) ---
#pragma unroll
        for (int kb = 0; kb < 4; ++kb) {
            uint32_t a[4];
            a[0] = packh2(sc[2 * kb][0],     sc[2 * kb][1]);
            a[1] = packh2(sc[2 * kb][2],     sc[2 * kb][3]);
            a[2] = packh2(sc[2 * kb + 1][0], sc[2 * kb + 1][1]);
            a[3] = packh2(sc[2 * kb + 1][2], sc[2 * kb + 1][3]);
#pragma unroll
            for (int nf = 0; nf < 8; ++nf) {
                const uint32_t* vr = VtW + (nf * 8 + g) * QPW + kb * 8 + t;
                mma_f16(oacc[nf], a, vr[0], vr[4]);
            }
        }
        __syncthreads();
    }

    lp0 += __shfl_xor_sync(0xffffffffu, lp0, 1);
    lp0 += __shfl_xor_sync(0xffffffffu, lp0, 2);
    lp1 += __shfl_xor_sync(0xffffffffu, lp1, 1);
    lp1 += __shfl_xor_sync(0xffffffffu, lp1, 2);
    const float inv0 = 1.0f / lp0;
    const float inv1 = 1.0f / lp1;

    const int r0 = q0 + w * 16 + g;
    uint32_t* cat0 = g_cat32 + ((size_t)b * S_ + r0) * 512 + h * 32;
    uint32_t* cat1 = cat0 + (size_t)8 * 512;
#pragma unroll
    for (int nf = 0; nf < 8; ++nf) {
        const int cw = nf * 4 + t;
        cat0[cw] = packh2(oacc[nf][0] * inv0, oacc[nf][1] * inv0);
        cat1[cw] = packh2(oacc[nf][2] * inv1, oacc[nf][3] * inv1);
    }
}

// ---------------------------------------------------------------------------
// Kernel 3: output projection, all-fp16 operands (cat + transposed Wo).
// ---------------------------------------------------------------------------
__global__ __launch_bounds__(256, 2) void out_mma(
    const float* __restrict__ bo, float* __restrict__ out)
{
    const int m0 = blockIdx.x * 128;
    const int n0 = blockIdx.y * 128;

    const uint32_t* Aw = g_cat32 + (size_t)m0 * 512;
    const __half* Wt = g_wot16 + (size_t)n0 * DOUT_;

    __shared__ uint32_t As[2][128 * APW];
    __shared__ uint32_t Bsm[2][128 * APW];

    const int tid = threadIdx.x;
    const int wid = tid >> 5, lane = tid & 31;
    const int wm = wid >> 2, wn = wid & 3;
    const int g = lane >> 2, t = lane & 3;

    const int lrow = tid >> 1, lw = (tid & 1) * 4;

    uint32_t aDst[2], bDst[2];
    aDst[0] = (uint32_t)__cvta_generic_to_shared(&As[0][lrow * APW + lw]);
    aDst[1] = (uint32_t)__cvta_generic_to_shared(&As[1][lrow * APW + lw]);
    bDst[0] = (uint32_t)__cvta_generic_to_shared(&Bsm[0][lrow * APW + lw]);
    bDst[1] = (uint32_t)__cvta_generic_to_shared(&Bsm[1][lrow * APW + lw]);

    float acc[4][4][4] = {};

    {
        cpa16(aDst[0], Aw + (size_t)lrow * 512 + lw);
        cpa16(bDst[0], Wt + (size_t)lrow * DOUT_ + lw * 2);
        cpa_commit();
    }

    const int NT = DOUT_ / 16;
#pragma unroll 1
    for (int it = 0; it < NT; ++it) {
        if (it + 1 < NT) {
            const int bi = (it + 1) & 1;
            cpa16(aDst[bi], Aw + (size_t)lrow * 512 + (it + 1) * 8 + lw);
            cpa16(bDst[bi], Wt + (size_t)lrow * DOUT_ + (it + 1) * 16 + lw * 2);
            cpa_commit();
            cpa_wait<1>();
        } else {
            cpa_wait<0>();
        }
        __syncthreads();

        const uint32_t* Ab = As[it & 1];
        const uint32_t* Bb = Bsm[it & 1];
        uint32_t a[4][4];
#pragma unroll
        for (int mf = 0; mf < 4; ++mf) {
            const int m = wm * 64 + mf * 16;
            a[mf][0] = Ab[(m + g)     * APW + t];
            a[mf][1] = Ab[(m + g + 8) * APW + t];
            a[mf][2] = Ab[(m + g)     * APW + t + 4];
            a[mf][3] = Ab[(m + g + 8) * APW + t + 4];
        }
#pragma unroll
        for (int nf = 0; nf < 4; ++nf) {
            const int n = wn * 32 + nf * 8 + g;
            const uint32_t b0 = Bb[n * APW + t];
            const uint32_t b1 = Bb[n * APW + t + 4];
#pragma unroll
            for (int mf = 0; mf < 4; ++mf)
                mma_f16(acc[mf][nf], a[mf], b0, b1);
        }
        __syncthreads();
    }

#pragma unroll
    for (int nf = 0; nf < 4; ++nf) {
        const int c = n0 + wn * 32 + nf * 8 + t * 2;
        const float b0v = bo[c], b1v = bo[c + 1];
#pragma unroll
        for (int mf = 0; mf < 4; ++mf) {
            const int r = m0 + wm * 64 + mf * 16 + g;
            *(float2*)(out + (size_t)r * DOUT_ + c) =
                make_float2(acc[mf][nf][0] + b0v, acc[mf][nf][1] + b1v);
            *(float2*)(out + (size_t)(r + 8) * DOUT_ + c) =
                make_float2(acc[mf][nf][2] + b0v, acc[mf][nf][3] + b1v);
        }
    }
}

// ---------------------------------------------------------------------------
extern "C" void kernel_launch(void* const* d_in, const int* in_sizes, int n_in,
                              void* d_out, int out_size)
{
    const float* q  = (const float*)d_in[0];
    const float* k  = (const float*)d_in[1];
    const float* v  = (const float*)d_in[2];
    const int* mask = (const int*)d_in[3];
    const float* Wq = (const float*)d_in[4];
    const float* bq = (const float*)d_in[5];
    const float* Wk = (const float*)d_in[6];
    const float* bk = (const float*)d_in[7];
    const float* Wv = (const float*)d_in[8];
    const float* bv = (const float*)d_in[9];
    const float* Wo = (const float*)d_in[10];
    const float* bo = (const float*)d_in[11];
    float* out = (float*)d_out;

    cudaFuncSetAttribute(attn_mma, cudaFuncAttributeMaxDynamicSharedMemorySize, SMEM_ATTN);

    dim3 gp1((B_ * S_ * D_) / (256 * 8), 3);
    prep_x<<<gp1, 256>>>(q, k, v);
    dim3 gp2(32, 32, 4);
    prep_wt<<<gp2, 256>>>(Wq, Wk, Wv, Wo);

    dim3 g1((B_ * S_) / 128, H_ / 2, 3);
    proj_mma<<<g1, 256>>>(bq, bk, bv);

    dim3 g2(S_ / 128, B_ * H_);
    attn_mma<<<g2, 256, SMEM_ATTN>>>(mask);

    dim3 g3((B_ * S_) / 128, DOUT_ / 128);
    out_mma<<<g3, 256>>>(bo, out);
}

// round 16
// speedup vs baseline: 2.1547x; 1.0846x over previous
#include <cuda_runtime.h>
#include <cuda_fp16.h>
#include <cstdint>

#define B_ 4
#define S_ 2048
#define D_ 1024
#define H_ 16
#define DK_ 64
#define DV_ 64
#define DOUT_ 1024

// Scratch, fp16: qh/kh (b,h,s,e); qh pre-scaled by 0.125*log2e.
// V stored TRANSPOSED: g_vht (b,h,e,s).  cat as packed half2 words.
__device__ __half  g_qh[(size_t)B_*H_*S_*DK_];
__device__ __half  g_kh[(size_t)B_*H_*S_*DK_];
__device__ __half  g_vht[(size_t)B_*H_*DV_*S_];
__device__ uint32_t g_cat32[(size_t)B_*S_*(H_*DV_/2)];

// fp16 pre-converted inputs/weights.
__device__ uint32_t g_x16[(size_t)3*B_*S_*D_/2];         // q,k,v as half2 words
__device__ __half   g_wt16[(size_t)3*H_*DK_*D_];         // Wq/Wk/Wv transposed [z][h][e][d]
__device__ __half   g_wot16[(size_t)DOUT_*DOUT_];        // Wo transposed [n][k]

// ---------------------------------------------------------------------------
// PTX helpers
// ---------------------------------------------------------------------------
__device__ __forceinline__ uint32_t packh2(float lo, float hi) {
    uint32_t u;
    asm("cvt.rn.f16x2.f32 %0, %1, %2;" : "=r"(u) : "f"(hi), "f"(lo));
    return u;
}

__device__ __forceinline__ void mma_f16(float* d, const uint32_t* a,
                                        uint32_t b0, uint32_t b1) {
    asm volatile(
        "mma.sync.aligned.m16n8k16.row.col.f32.f16.f16.f32 "
        "{%0,%1,%2,%3}, {%4,%5,%6,%7}, {%8,%9}, {%0,%1,%2,%3};\n"
        : "+f"(d[0]), "+f"(d[1]), "+f"(d[2]), "+f"(d[3])
        : "r"(a[0]), "r"(a[1]), "r"(a[2]), "r"(a[3]), "r"(b0), "r"(b1));
}

// ldmatrix x4: four 8x8 b16 matrices; lane groups 0-7/8-15/16-23/24-31 supply
// the row addresses of matrices 0..3; result ri = matrix i with the standard
// (g = lane>>2, t = lane&3) fragment distribution.
__device__ __forceinline__ void ldsm_x4(uint32_t& r0, uint32_t& r1,
                                        uint32_t& r2, uint32_t& r3, uint32_t addr) {
    asm volatile("ldmatrix.sync.aligned.m8n8.x4.shared.b16 {%0,%1,%2,%3}, [%4];"
                 : "=r"(r0), "=r"(r1), "=r"(r2), "=r"(r3) : "r"(addr));
}

__device__ __forceinline__ void cpa16(uint32_t dst, const void* src) {
    asm volatile("cp.async.cg.shared.global [%0], [%1], 16;\n" :: "r"(dst), "l"(src));
}
__device__ __forceinline__ void cpa_commit() {
    asm volatile("cp.async.commit_group;\n");
}
template <int N>
__device__ __forceinline__ void cpa_wait() {
    asm volatile("cp.async.wait_group %0;\n" :: "n"(N));
}

#define QSCALE (0.125f * 1.4426950408889634f)

// ---------------------------------------------------------------------------
// Prep 1: q/k/v fp32 -> fp16 (half2 words), same layout.
// ---------------------------------------------------------------------------
__global__ __launch_bounds__(256) void prep_x(
    const float* __restrict__ q, const float* __restrict__ k, const float* __restrict__ v)
{
    const int z = blockIdx.y;
    const float* s = (z == 0) ? q : (z == 1) ? k : v;
    uint32_t* d = g_x16 + (size_t)z * (B_ * S_ * D_ / 2);
    const size_t i = ((size_t)blockIdx.x * 256 + threadIdx.x) * 8;
    float4 v0 = *(const float4*)(s + i);
    float4 v1 = *(const float4*)(s + i + 4);
    uint4 u;
    u.x = packh2(v0.x, v0.y);
    u.y = packh2(v0.z, v0.w);
    u.z = packh2(v1.x, v1.y);
    u.w = packh2(v1.z, v1.w);
    *(uint4*)(d + i / 2) = u;
}

// ---------------------------------------------------------------------------
// Prep 2: weight transpose to fp16.  z<3: Wq/Wk/Wv [h][d][e] -> [z][h][e][d];
// z==3: Wo [k][n] -> [n][k].  32x32 tiles via smem.
// ---------------------------------------------------------------------------
__global__ __launch_bounds__(256) void prep_wt(
    const float* __restrict__ Wq, const float* __restrict__ Wk,
    const float* __restrict__ Wv, const float* __restrict__ Wo)
{
    __shared__ float ts[32][33];
    const int z = blockIdx.z;
    const int tid = threadIdx.x;
    const int r = tid >> 5, c = tid & 31;

    const float* in;
    __half* out;
    int istride, ostride;
    if (z < 3) {
        const float* W = (z == 0) ? Wq : (z == 1) ? Wk : Wv;
        const int h = blockIdx.y >> 1, et = blockIdx.y & 1;
        in  = W + ((size_t)h * D_ + blockIdx.x * 32) * DK_ + et * 32;
        out = g_wt16 + (size_t)z * (H_ * DK_ * D_)
              + ((size_t)h * DK_ + et * 32) * D_ + blockIdx.x * 32;
        istride = DK_; ostride = D_;
    } else {
        in  = Wo + (size_t)(blockIdx.x * 32) * DOUT_ + blockIdx.y * 32;
        out = g_wot16 + (size_t)(blockIdx.y * 32) * DOUT_ + blockIdx.x * 32;
        istride = DOUT_; ostride = DOUT_;
    }

#pragma unroll
    for (int i = 0; i < 4; ++i)
        ts[r + 8 * i][c] = in[(size_t)(r + 8 * i) * istride + c];
    __syncthreads();
#pragma unroll
    for (int i = 0; i < 4; ++i)
        out[(size_t)(r + 8 * i) * ostride + c] = __float2half_rn(ts[c][r + 8 * i]);
}

// fp16 GEMM tiles: 128 rows x 16 halves (8 words + 4 pad).
#define APW 12

// ---------------------------------------------------------------------------
// Kernel 1: per-head projections, all-fp16 operands, BK=16, ldmatrix frags.
// z==2 (V) epilogue stores TRANSPOSED (b,h,e,s).
// ---------------------------------------------------------------------------
__global__ __launch_bounds__(256, 2) void proj_mma(
    const float* __restrict__ bq, const float* __restrict__ bk, const float* __restrict__ bv)
{
    const int z = blockIdx.z;
    const float* bias = (z == 0) ? bq : (z == 1) ? bk : bv;
    const float osc   = (z == 0) ? QSCALE : 1.0f;

    const int h0 = blockIdx.y * 2;
    const int m0 = blockIdx.x * 128;
    const int b  = m0 >> 11;
    const int s0 = m0 & (S_ - 1);

    const uint32_t* Xw = g_x16 + (size_t)z * (B_ * S_ * D_ / 2) + (size_t)m0 * (D_ / 2);
    const __half* Wt = g_wt16 + (size_t)z * (H_ * DK_ * D_) + (size_t)(h0 * 64) * D_;

    __shared__ uint32_t As[2][128 * APW];
    __shared__ uint32_t Bsm[2][128 * APW];

    const int tid = threadIdx.x;
    const int wid = tid >> 5, lane = tid & 31;
    const int wm = wid >> 2, wn = wid & 3;
    const int g = lane >> 2, t = lane & 3;

    const int lrow = tid >> 1, lw = (tid & 1) * 4;

    uint32_t aDst[2], bDst[2];
    aDst[0] = (uint32_t)__cvta_generic_to_shared(&As[0][lrow * APW + lw]);
    aDst[1] = (uint32_t)__cvta_generic_to_shared(&As[1][lrow * APW + lw]);
    bDst[0] = (uint32_t)__cvta_generic_to_shared(&Bsm[0][lrow * APW + lw]);
    bDst[1] = (uint32_t)__cvta_generic_to_shared(&Bsm[1][lrow * APW + lw]);

    // ldmatrix lane bases (bytes).  A: m16k16 tiles (mf); matrices =
    // (rows0-7,k0)(rows8-15,k0)(rows0-7,k8)(rows8-15,k8).
    // B: n-pair tiles; matrices = (nf0,k0)(nf0,k8)(nf1,k0)(nf1,k8).
    const uint32_t aBase[2] = {
        (uint32_t)__cvta_generic_to_shared(&As[0][0]),
        (uint32_t)__cvta_generic_to_shared(&As[1][0]) };
    const uint32_t bBase[2] = {
        (uint32_t)__cvta_generic_to_shared(&Bsm[0][0]),
        (uint32_t)__cvta_generic_to_shared(&Bsm[1][0]) };
    const uint32_t alane = 4 * (((wm * 64 + (lane & 7) + ((lane >> 3) & 1) * 8) * APW)
                                + ((lane >> 4) & 1) * 4);
    const uint32_t blane = 4 * (((wn * 32 + ((lane >> 4) & 1) * 8 + (lane & 7)) * APW)
                                + ((lane >> 3) & 1) * 4);

    float acc[4][4][4] = {};

    {
        cpa16(aDst[0], Xw + (size_t)lrow * (D_ / 2) + lw);
        cpa16(bDst[0], Wt + (size_t)lrow * D_ + lw * 2);
        cpa_commit();
    }

    const int NT = D_ / 16;
#pragma unroll 1
    for (int it = 0; it < NT; ++it) {
        if (it + 1 < NT) {
            const int bi = (it + 1) & 1;
            cpa16(aDst[bi], Xw + (size_t)lrow * (D_ / 2) + (it + 1) * 8 + lw);
            cpa16(bDst[bi], Wt + (size_t)lrow * D_ + (it + 1) * 16 + lw * 2);
            cpa_commit();
            cpa_wait<1>();
        } else {
            cpa_wait<0>();
        }
        __syncthreads();

        const uint32_t aB = aBase[it & 1] + alane;
        const uint32_t bB = bBase[it & 1] + blane;
        uint32_t a[4][4];
#pragma unroll
        for (int mf = 0; mf < 4; ++mf)
            ldsm_x4(a[mf][0], a[mf][1], a[mf][2], a[mf][3], aB + mf * (16 * APW * 4));
#pragma unroll
        for (int np = 0; np < 2; ++np) {
            uint32_t b0, b1, b2, b3;
            ldsm_x4(b0, b1, b2, b3, bB + np * (16 * APW * 4));
#pragma unroll
            for (int mf = 0; mf < 4; ++mf) {
                mma_f16(acc[mf][2 * np],     a[mf], b0, b1);
                mma_f16(acc[mf][2 * np + 1], a[mf], b2, b3);
            }
        }
        __syncthreads();
    }

    if (z == 2) {
#pragma unroll
        for (int nf = 0; nf < 4; ++nf) {
            const int c = wn * 32 + nf * 8 + t * 2;
            const int h = h0 + (c >> 6);
            const int e = c & 63;
            const float b0v = bias[h * DK_ + e];
            const float b1v = bias[h * DK_ + e + 1];
            __half* O0 = g_vht + ((size_t)(b * H_ + h) * DK_ + e) * S_ + s0;
            __half* O1 = O0 + S_;
#pragma unroll
            for (int mf = 0; mf < 4; ++mf) {
                const int r = wm * 64 + mf * 16 + g;
                O0[r]     = __float2half_rn(acc[mf][nf][0] + b0v);
                O1[r]     = __float2half_rn(acc[mf][nf][1] + b1v);
                O0[r + 8] = __float2half_rn(acc[mf][nf][2] + b0v);
                O1[r + 8] = __float2half_rn(acc[mf][nf][3] + b1v);
            }
        }
    } else {
        __half* Out = (z == 0) ? g_qh : g_kh;
#pragma unroll
        for (int nf = 0; nf < 4; ++nf) {
            const int c = wn * 32 + nf * 8 + t * 2;
            const int h = h0 + (c >> 6);
            const int e = c & 63;
            const float b0v = bias[h * DK_ + e];
            const float b1v = bias[h * DK_ + e + 1];
            __half* Ob = Out + ((size_t)(b * H_ + h) * S_ + s0) * DK_ + e;
#pragma unroll
            for (int mf = 0; mf < 4; ++mf) {
                const int r = wm * 64 + mf * 16 + g;
                *(uint32_t*)(Ob + (size_t)r * DK_) =
                    packh2((acc[mf][nf][0] + b0v) * osc, (acc[mf][nf][1] + b1v) * osc);
                *(uint32_t*)(Ob + (size_t)(r + 8) * DK_) =
                    packh2((acc[mf][nf][2] + b0v) * osc, (acc[mf][nf][3] + b1v) * osc);
            }
        }
    }
}

// ---------------------------------------------------------------------------
// Kernel 2: fp16 flash attention; fragment loads via ldmatrix.x4.
// ---------------------------------------------------------------------------
#define QPW 36
#define KBUFW (64 * QPW)
#define SM_K 4608
#define SM_V (SM_K + 2 * KBUFW)
#define SM_M (SM_V + 2 * KBUFW)
#define SMEM_ATTN ((SM_M + 128) * 4)

__global__ __launch_bounds__(256, 2) void attn_mma(const int* __restrict__ mask)
{
    extern __shared__ uint32_t smw[];
    uint32_t* Qs = smw;
    int*      Msall = (int*)(smw + SM_M);

    const int bh = blockIdx.y;
    const int b = bh >> 4, h = bh & 15;
    const int q0 = blockIdx.x * 128;

    const __half* Qg = g_qh + ((size_t)bh * S_ + q0) * DK_;
    const __half* Kg = g_kh + (size_t)bh * S_ * DK_;
    const __half* Vtg = g_vht + (size_t)bh * DV_ * S_;
    const int* mk = mask + (size_t)b * S_;

    const int tid = threadIdx.x;
    const int w = tid >> 5, lane = tid & 31;
    const int g = lane >> 2, t = lane & 3;

    const uint32_t* Qg32 = (const uint32_t*)Qg;
    for (int i = tid; i < 1024; i += 256) {
        const int row = i >> 3, ws = (i & 7) * 4;
        *(uint4*)(&Qs[row * QPW + ws]) = *(const uint4*)(Qg32 + row * 32 + ws);
    }

    {
#pragma unroll
        for (int j = 0; j < 2; ++j) {
            const int idx = tid + j * 256;
            const int row = idx >> 3, hc = (idx & 7) * 8;
            cpa16((uint32_t)__cvta_generic_to_shared(smw + SM_K + row * QPW + hc / 2),
                  Kg + (size_t)row * DK_ + hc);
            cpa16((uint32_t)__cvta_generic_to_shared(smw + SM_V + row * QPW + hc / 2),
                  Vtg + (size_t)row * S_ + hc);
        }
        if (tid < 16)
            cpa16((uint32_t)__cvta_generic_to_shared((uint32_t*)(Msall) + tid * 4),
                  mk + tid * 4);
        cpa_commit();
    }

    float oacc[8][4] = {};
    float mold0 = -1e30f, mold1 = -1e30f;
    float lp0 = 0.0f, lp1 = 0.0f;

    // ldmatrix lane bases (bytes).
    const uint32_t smb32 = (uint32_t)__cvta_generic_to_shared(smw);
    const uint32_t qlm = smb32 +
        4 * (((w * 16 + (lane & 7) + ((lane >> 3) & 1) * 8) * QPW) + ((lane >> 4) & 1) * 4);
    const uint32_t kvlane =
        4 * (((((lane >> 4) & 1) * 8 + (lane & 7)) * QPW) + ((lane >> 3) & 1) * 4);

    const int NCH = S_ / 64;
#pragma unroll 1
    for (int chunk = 0; chunk < NCH; ++chunk) {
        const int bi = chunk & 1;

        if (chunk + 1 < NCH) {
            const int kc = (chunk + 1) * 64;
            const int bo2 = bi ^ 1;
#pragma unroll
            for (int j = 0; j < 2; ++j) {
                const int idx = tid + j * 256;
                const int row = idx >> 3, hc = (idx & 7) * 8;
                cpa16((uint32_t)__cvta_generic_to_shared(
                          smw + SM_K + bo2 * KBUFW + row * QPW + hc / 2),
                      Kg + (size_t)(kc + row) * DK_ + hc);
                cpa16((uint32_t)__cvta_generic_to_shared(
                          smw + SM_V + bo2 * KBUFW + row * QPW + hc / 2),
                      Vtg + (size_t)row * S_ + kc + hc);
            }
            if (tid < 16)
                cpa16((uint32_t)__cvta_generic_to_shared(
                          (uint32_t*)(Msall) + bo2 * 64 + tid * 4),
                      mk + kc + tid * 4);
            cpa_commit();
            cpa_wait<1>();
        } else {
            cpa_wait<0>();
        }
        __syncthreads();

        const uint32_t klm = smb32 + 4 * (SM_K + bi * KBUFW) + kvlane;
        const uint32_t vlm = smb32 + 4 * (SM_V + bi * KBUFW) + kvlane;
        const int* Mb = Msall + bi * 64;

        // --- scores: S = Q @ K^T ---
        float sc[8][4] = {};
#pragma unroll
        for (int kb = 0; kb < 4; ++kb) {
            uint32_t a[4];
            ldsm_x4(a[0], a[1], a[2], a[3], qlm + kb * 32);
#pragma unroll
            for (int np = 0; np < 4; ++np) {
                uint32_t b0, b1, b2, b3;
                ldsm_x4(b0, b1, b2, b3, klm + np * (16 * QPW * 4) + kb * 32);
                mma_f16(sc[2 * np],     a, b0, b1);
                mma_f16(sc[2 * np + 1], a, b2, b3);
            }
        }

        // --- mask + row max ---
        float tm0 = -1e30f, tm1 = -1e30f;
#pragma unroll
        for (int nf = 0; nf < 8; ++nf) {
            const int ma = Mb[nf * 8 + 2 * t];
            const int mb = Mb[nf * 8 + 2 * t + 1];
            if (!ma) { sc[nf][0] = -1e30f; sc[nf][2] = -1e30f; }
            if (!mb) { sc[nf][1] = -1e30f; sc[nf][3] = -1e30f; }
            tm0 = fmaxf(tm0, fmaxf(sc[nf][0], sc[nf][1]));
            tm1 = fmaxf(tm1, fmaxf(sc[nf][2], sc[nf][3]));
        }
        tm0 = fmaxf(tm0, __shfl_xor_sync(0xffffffffu, tm0, 1));
        tm0 = fmaxf(tm0, __shfl_xor_sync(0xffffffffu, tm0, 2));
        tm1 = fmaxf(tm1, __shfl_xor_sync(0xffffffffu, tm1, 1));
        tm1 = fmaxf(tm1, __shfl_xor_sync(0xffffffffu, tm1, 2));

        const float mn0 = fmaxf(mold0, tm0);
        const float mn1 = fmaxf(mold1, tm1);
        const float f0 = exp2f(mold0 - mn0);
        const float f1 = exp2f(mold1 - mn1);
        mold0 = mn0; mold1 = mn1;

        // --- exp + partial sums ---
        float cs0 = 0.0f, cs1 = 0.0f;
#pragma unroll
        for (int nf = 0; nf < 8; ++nf) {
            sc[nf][0] = exp2f(sc[nf][0] - mn0);
            sc[nf][1] = exp2f(sc[nf][1] - mn0);
            sc[nf][2] = exp2f(sc[nf][2] - mn1);
            sc[nf][3] = exp2f(sc[nf][3] - mn1);
            cs0 += sc[nf][0] + sc[nf][1];
            cs1 += sc[nf][2] + sc[nf][3];
        }
        lp0 = lp0 * f0 + cs0;
        lp1 = lp1 * f1 + cs1;

#pragma unroll
        for (int nf = 0; nf < 8; ++nf) {
            oacc[nf][0] *= f0; oacc[nf][1] *= f0;
            oacc[nf][2] *= f1; oacc[nf][3] *= f1;
        }

        // --- O += P @ V via V^T ldmatrix frags ---
#pragma unroll
        for (int kb = 0; kb < 4; ++kb) {
            uint32_t a[4];
            a[0] = packh2(sc[2 * kb][0],     sc[2 * kb][1]);
            a[1] = packh2(sc[2 * kb][2],     sc[2 * kb][3]);
            a[2] = packh2(sc[2 * kb + 1][0], sc[2 * kb + 1][1]);
            a[3] = packh2(sc[2 * kb + 1][2], sc[2 * kb + 1][3]);
#pragma unroll
            for (int np = 0; np < 4; ++np) {
                uint32_t b0, b1, b2, b3;
                ldsm_x4(b0, b1, b2, b3, vlm + np * (16 * QPW * 4) + kb * 32);
                mma_f16(oacc[2 * np],     a, b0, b1);
                mma_f16(oacc[2 * np + 1], a, b2, b3);
            }
        }
        __syncthreads();
    }

    lp0 += __shfl_xor_sync(0xffffffffu, lp0, 1);
    lp0 += __shfl_xor_sync(0xffffffffu, lp0, 2);
    lp1 += __shfl_xor_sync(0xffffffffu, lp1, 1);
    lp1 += __shfl_xor_sync(0xffffffffu, lp1, 2);
    const float inv0 = 1.0f / lp0;
    const float inv1 = 1.0f / lp1;

    const int r0 = q0 + w * 16 + g;
    uint32_t* cat0 = g_cat32 + ((size_t)b * S_ + r0) * 512 + h * 32;
    uint32_t* cat1 = cat0 + (size_t)8 * 512;
#pragma unroll
    for (int nf = 0; nf < 8; ++nf) {
        const int cw = nf * 4 + t;
        cat0[cw] = packh2(oacc[nf][0] * inv0, oacc[nf][1] * inv0);
        cat1[cw] = packh2(oacc[nf][2] * inv1, oacc[nf][3] * inv1);
    }
}

// ---------------------------------------------------------------------------
// Kernel 3: output projection, all-fp16 operands, ldmatrix frags.
// ---------------------------------------------------------------------------
__global__ __launch_bounds__(256, 2) void out_mma(
    const float* __restrict__ bo, float* __restrict__ out)
{
    const int m0 = blockIdx.x * 128;
    const int n0 = blockIdx.y * 128;

    const uint32_t* Aw = g_cat32 + (size_t)m0 * 512;
    const __half* Wt = g_wot16 + (size_t)n0 * DOUT_;

    __shared__ uint32_t As[2][128 * APW];
    __shared__ uint32_t Bsm[2][128 * APW];

    const int tid = threadIdx.x;
    const int wid = tid >> 5, lane = tid & 31;
    const int wm = wid >> 2, wn = wid & 3;
    const int g = lane >> 2, t = lane & 3;

    const int lrow = tid >> 1, lw = (tid & 1) * 4;

    uint32_t aDst[2], bDst[2];
    aDst[0] = (uint32_t)__cvta_generic_to_shared(&As[0][lrow * APW + lw]);
    aDst[1] = (uint32_t)__cvta_generic_to_shared(&As[1][lrow * APW + lw]);
    bDst[0] = (uint32_t)__cvta_generic_to_shared(&Bsm[0][lrow * APW + lw]);
    bDst[1] = (uint32_t)__cvta_generic_to_shared(&Bsm[1][lrow * APW + lw]);

    const uint32_t aBase[2] = {
        (uint32_t)__cvta_generic_to_shared(&As[0][0]),
        (uint32_t)__cvta_generic_to_shared(&As[1][0]) };
    const uint32_t bBase[2] = {
        (uint32_t)__cvta_generic_to_shared(&Bsm[0][0]),
        (uint32_t)__cvta_generic_to_shared(&Bsm[1][0]) };
    const uint32_t alane = 4 * (((wm * 64 + (lane & 7) + ((lane >> 3) & 1) * 8) * APW)
                                + ((lane >> 4) & 1) * 4);
    const uint32_t blane = 4 * (((wn * 32 + ((lane >> 4) & 1) * 8 + (lane & 7)) * APW)
                                + ((lane >> 3) & 1) * 4);

    float acc[4][4][4] = {};

    {
        cpa16(aDst[0], Aw + (size_t)lrow * 512 + lw);
        cpa16(bDst[0], Wt + (size_t)lrow * DOUT_ + lw * 2);
        cpa_commit();
    }

    const int NT = DOUT_ / 16;
#pragma unroll 1
    for (int it = 0; it < NT; ++it) {
        if (it + 1 < NT) {
            const int bi = (it + 1) & 1;
            cpa16(aDst[bi], Aw + (size_t)lrow * 512 + (it + 1) * 8 + lw);
            cpa16(bDst[bi], Wt + (size_t)lrow * DOUT_ + (it + 1) * 16 + lw * 2);
            cpa_commit();
            cpa_wait<1>();
        } else {
            cpa_wait<0>();
        }
        __syncthreads();

        const uint32_t aB = aBase[it & 1] + alane;
        const uint32_t bB = bBase[it & 1] + blane;
        uint32_t a[4][4];
#pragma unroll
        for (int mf = 0; mf < 4; ++mf)
            ldsm_x4(a[mf][0], a[mf][1], a[mf][2], a[mf][3], aB + mf * (16 * APW * 4));
#pragma unroll
        for (int np = 0; np < 2; ++np) {
            uint32_t b0, b1, b2, b3;
            ldsm_x4(b0, b1, b2, b3, bB + np * (16 * APW * 4));
#pragma unroll
            for (int mf = 0; mf < 4; ++mf) {
                mma_f16(acc[mf][2 * np],     a[mf], b0, b1);
                mma_f16(acc[mf][2 * np + 1], a[mf], b2, b3);
            }
        }
        __syncthreads();
    }

#pragma unroll
    for (int nf = 0; nf < 4; ++nf) {
        const int c = n0 + wn * 32 + nf * 8 + t * 2;
        const float b0v = bo[c], b1v = bo[c + 1];
#pragma unroll
        for (int mf = 0; mf < 4; ++mf) {
            const int r = m0 + wm * 64 + mf * 16 + g;
            *(float2*)(out + (size_t)r * DOUT_ + c) =
                make_float2(acc[mf][nf][0] + b0v, acc[mf][nf][1] + b1v);
            *(float2*)(out + (size_t)(r + 8) * DOUT_ + c) =
                make_float2(acc[mf][nf][2] + b0v, acc[mf][nf][3] + b1v);
        }
    }
}

// ---------------------------------------------------------------------------
extern "C" void kernel_launch(void* const* d_in, const int* in_sizes, int n_in,
                              void* d_out, int out_size)
{
    const float* q  = (const float*)d_in[0];
    const float* k  = (const float*)d_in[1];
    const float* v  = (const float*)d_in[2];
    const int* mask = (const int*)d_in[3];
    const float* Wq = (const float*)d_in[4];
    const float* bq = (const float*)d_in[5];
    const float* Wk = (const float*)d_in[6];
    const float* bk = (const float*)d_in[7];
    const float* Wv = (const float*)d_in[8];
    const float* bv = (const float*)d_in[9];
    const float* Wo = (const float*)d_in[10];
    const float* bo = (const float*)d_in[11];
    float* out = (float*)d_out;

    cudaFuncSetAttribute(attn_mma, cudaFuncAttributeMaxDynamicSharedMemorySize, SMEM_ATTN);

    dim3 gp1((B_ * S_ * D_) / (256 * 8), 3);
    prep_x<<<gp1, 256>>>(q, k, v);
    dim3 gp2(32, 32, 4);
    prep_wt<<<gp2, 256>>>(Wq, Wk, Wv, Wo);

    dim3 g1((B_ * S_) / 128, H_ / 2, 3);
    proj_mma<<<g1, 256>>>(bq, bk, bv);

    dim3 g2(S_ / 128, B_ * H_);
    attn_mma<<<g2, 256, SMEM_ATTN>>>(mask);

    dim3 g3((B_ * S_) / 128, DOUT_ / 128);
    out_mma<<<g3, 256>>>(bo, out);
}